// round 5
// baseline (speedup 1.0000x reference)
#include <cuda_runtime.h>
#include <math.h>
#include <stdint.h>

#define N_NODES 50000
#define NEG_SLOPE 0.2f
#define MAX_E 1200000
#define SCAN_CHUNK 512
#define NUM_SCAN_BLOCKS ((N_NODES + SCAN_CHUNK - 1) / SCAN_CHUNK)

// ---------------- device scratch (no allocs allowed) ----------------
__device__ float g_h1 [(size_t)N_NODES * 128];
__device__ float g_hid[(size_t)N_NODES * 128];
__device__ float g_h2 [(size_t)N_NODES * 64];
__device__ float g_asrc[N_NODES];
__device__ float g_adst[N_NODES];
__device__ int   g_cnt[N_NODES];
__device__ int   g_rowptr[N_NODES + 1];
__device__ int   g_cur[N_NODES];
__device__ int   g_col[MAX_E];
__device__ int   g_bsum[NUM_SCAN_BLOCKS + 1];
__device__ int   g_idx64;

__device__ __forceinline__ float leaky_exp(float e) {
    e = (e > 0.f) ? e : NEG_SLOPE * e;
    return __expf(e);
}

// ---------------- dtype detection for edge_index (int32 vs int64) ----------------
__global__ void detect_idx_dtype(const int* __restrict__ ei32) {
    int z = 1;
    for (int i = 1; i < 256; i += 2)
        if (ei32[i] != 0) { z = 0; break; }
    g_idx64 = z;
}

// ---------------- CSR build ----------------
__global__ void zero_counts(int* __restrict__ cnt) {
    int i = blockIdx.x * blockDim.x + threadIdx.x;
    if (i < N_NODES) cnt[i] = 0;
}

__global__ void count_edges(const void* __restrict__ ei, int E, int* __restrict__ cnt) {
    int i = blockIdx.x * blockDim.x + threadIdx.x;
    if (i >= E) return;
    int d;
    if (g_idx64) d = (int)((const long long*)ei)[(size_t)E + i];
    else         d = ((const int*)ei)[E + i];
    atomicAdd(cnt + d, 1);
}

__global__ void scan_block(const int* __restrict__ cnt, int* __restrict__ rowptr,
                           int* __restrict__ bsum) {
    __shared__ int sm[SCAN_CHUNK];
    int b = blockIdx.x, t = threadIdx.x;
    int i = b * SCAN_CHUNK + t;
    int v = (i < N_NODES) ? cnt[i] : 0;
    sm[t] = v;
    __syncthreads();
#pragma unroll
    for (int o = 1; o < SCAN_CHUNK; o <<= 1) {
        int x = (t >= o) ? sm[t - o] : 0;
        __syncthreads();
        sm[t] += x;
        __syncthreads();
    }
    if (i < N_NODES) rowptr[i] = sm[t] - v;  // exclusive
    if (t == SCAN_CHUNK - 1) bsum[b] = sm[t];
}

__global__ void scan_bsums(int* __restrict__ bsum) {
    __shared__ int sm[NUM_SCAN_BLOCKS];
    int t = threadIdx.x;
    if (t < NUM_SCAN_BLOCKS) sm[t] = bsum[t];
    __syncthreads();
    if (t == 0) {
        int acc = 0;
        for (int i = 0; i < NUM_SCAN_BLOCKS; i++) { int v = sm[i]; sm[i] = acc; acc += v; }
    }
    __syncthreads();
    if (t < NUM_SCAN_BLOCKS) bsum[t] = sm[t];
}

__global__ void add_offsets(int* __restrict__ rowptr, const int* __restrict__ bsum,
                            int* __restrict__ cur, int E) {
    int i = blockIdx.x * blockDim.x + threadIdx.x;
    if (i < N_NODES) {
        int r = rowptr[i] + bsum[i / SCAN_CHUNK];
        rowptr[i] = r;
        cur[i] = r;
    }
    if (i == 0) rowptr[N_NODES] = E;
}

__global__ void scatter_edges(const void* __restrict__ ei, int E,
                              int* __restrict__ cur, int* __restrict__ col) {
    int i = blockIdx.x * blockDim.x + threadIdx.x;
    if (i >= E) return;
    int s, d;
    if (g_idx64) {
        const long long* p = (const long long*)ei;
        s = (int)p[i];
        d = (int)p[(size_t)E + i];
    } else {
        const int* p = (const int*)ei;
        s = p[i];
        d = p[E + i];
    }
    int pos = atomicAdd(cur + d, 1);
    col[pos] = s;
}

// ---------------- 3xTF32 tensor-core GEMM ----------------
__device__ __forceinline__ void split_tf32(float v, uint32_t& big, uint32_t& sml) {
    uint32_t b;
    asm("cvt.rna.tf32.f32 %0, %1;" : "=r"(b) : "f"(v));
    float s = v - __uint_as_float(b);
    uint32_t sm_;
    asm("cvt.rna.tf32.f32 %0, %1;" : "=r"(sm_) : "f"(s));
    big = b; sml = sm_;
}

__device__ __forceinline__ void mma_tf32(float* c, const uint32_t* a, const uint32_t* b) {
    asm volatile(
        "mma.sync.aligned.m16n8k8.row.col.f32.tf32.tf32.f32 "
        "{%0,%1,%2,%3}, {%4,%5,%6,%7}, {%8,%9}, {%0,%1,%2,%3};"
        : "+f"(c[0]), "+f"(c[1]), "+f"(c[2]), "+f"(c[3])
        : "r"(a[0]), "r"(a[1]), "r"(a[2]), "r"(a[3]), "r"(b[0]), "r"(b[1]));
}

// A [M,K] row-major, B [K,N] row-major, C [M,N]. K%BK==0, BN==N (single block col).
// 8 warps (256 thr), warp grid WR=4 x WC=2, warp tile (BM/WR=32) x (BN/WC).
template <int BM, int BN, int BK>
__global__ void tf32_gemm(const float* __restrict__ A, const float* __restrict__ B,
                          float* __restrict__ C, int M, int N, int K) {
    constexpr int WR = 4, WC = 2;
    constexpr int nThreads = WR * WC * 32;
    constexpr int WM = BM / WR;          // 32
    constexpr int WN = BN / WC;          // 64 or 32
    constexpr int MT = WM / 16;          // 2
    constexpr int NT = WN / 8;           // 8 or 4
    constexpr int APAD = 4, BPAD = 8;

    __shared__ float As[BM][BK + APAD];
    __shared__ float Bs[BK][BN + BPAD];

    int tid = threadIdx.x;
    int wid = tid >> 5;
    int lane = tid & 31;
    int wr = wid / WC, wc = wid % WC;
    int row0 = blockIdx.y * BM;

    float acc[MT][NT][4];
#pragma unroll
    for (int i = 0; i < MT; i++)
#pragma unroll
        for (int j = 0; j < NT; j++)
#pragma unroll
            for (int q = 0; q < 4; q++) acc[i][j][q] = 0.f;

    for (int k0 = 0; k0 < K; k0 += BK) {
        // A tile: BM x BK, float4 loads
#pragma unroll
        for (int i = tid; i < BM * BK / 4; i += nThreads) {
            int r = i / (BK / 4);
            int c4 = i % (BK / 4);
            int gr = row0 + r;
            float4 v = make_float4(0.f, 0.f, 0.f, 0.f);
            if (gr < M) v = *(const float4*)(A + (size_t)gr * K + k0 + c4 * 4);
            *(float4*)&As[r][c4 * 4] = v;
        }
        // B tile: BK x BN
#pragma unroll
        for (int i = tid; i < BK * BN / 4; i += nThreads) {
            int r = i / (BN / 4);
            int c4 = i % (BN / 4);
            *(float4*)&Bs[r][c4 * 4] = *(const float4*)(B + (size_t)(k0 + r) * N + c4 * 4);
        }
        __syncthreads();

#pragma unroll
        for (int ks = 0; ks < BK / 8; ks++) {
            uint32_t abig[MT][4], asml[MT][4];
#pragma unroll
            for (int mt = 0; mt < MT; mt++) {
                int rbase = wr * WM + mt * 16 + (lane >> 2);
                int cc = ks * 8 + (lane & 3);
                split_tf32(As[rbase][cc],         abig[mt][0], asml[mt][0]);
                split_tf32(As[rbase + 8][cc],     abig[mt][1], asml[mt][1]);
                split_tf32(As[rbase][cc + 4],     abig[mt][2], asml[mt][2]);
                split_tf32(As[rbase + 8][cc + 4], abig[mt][3], asml[mt][3]);
            }
#pragma unroll
            for (int nt = 0; nt < NT; nt++) {
                int cb = wc * WN + nt * 8 + (lane >> 2);
                int kk = ks * 8 + (lane & 3);
                uint32_t bbig[2], bsml[2];
                split_tf32(Bs[kk][cb],     bbig[0], bsml[0]);
                split_tf32(Bs[kk + 4][cb], bbig[1], bsml[1]);
#pragma unroll
                for (int mt = 0; mt < MT; mt++) {
                    mma_tf32(acc[mt][nt], abig[mt], bbig);
                    mma_tf32(acc[mt][nt], abig[mt], bsml);
                    mma_tf32(acc[mt][nt], asml[mt], bbig);
                }
            }
        }
        __syncthreads();
    }

    // epilogue
#pragma unroll
    for (int mt = 0; mt < MT; mt++) {
#pragma unroll
        for (int nt = 0; nt < NT; nt++) {
            int row = row0 + wr * WM + mt * 16 + (lane >> 2);
            int col = wc * WN + nt * 8 + (lane & 3) * 2;
            if (row < M)
                *(float2*)(C + (size_t)row * N + col) =
                    make_float2(acc[mt][nt][0], acc[mt][nt][1]);
            if (row + 8 < M)
                *(float2*)(C + (size_t)(row + 8) * N + col) =
                    make_float2(acc[mt][nt][2], acc[mt][nt][3]);
        }
    }
}

// ---------------- per-node attention dots ----------------
template <int C>
__global__ void node_dots(const float* __restrict__ h,
                          const float* __restrict__ att_s, const float* __restrict__ att_d,
                          float* __restrict__ asrc, float* __restrict__ adst) {
    int warp = (blockIdx.x * blockDim.x + threadIdx.x) >> 5;
    int lane = threadIdx.x & 31;
    if (warp >= N_NODES) return;
    float ss = 0.f, sd = 0.f;
    const float* hrow = h + (size_t)warp * C;
#pragma unroll
    for (int j = lane; j < C; j += 32) {
        float v = hrow[j];
        ss += v * att_s[j];
        sd += v * att_d[j];
    }
#pragma unroll
    for (int o = 16; o > 0; o >>= 1) {
        ss += __shfl_down_sync(0xffffffffu, ss, o);
        sd += __shfl_down_sync(0xffffffffu, sd, o);
    }
    if (lane == 0) {
        asrc[warp] = ss;
        adst[warp] = sd;
    }
}

// ---------------- fused gather-aggregate layer 1 (C=128): softmax + bias + ReLU ----------------
__global__ void agg1(const int* __restrict__ rowptr, const int* __restrict__ col,
                     const float* __restrict__ h, const float* __restrict__ asrc,
                     const float* __restrict__ adst, const float* __restrict__ bias,
                     float* __restrict__ out) {
    int warp = (blockIdx.x * blockDim.x + threadIdx.x) >> 5;
    int lane = threadIdx.x & 31;
    if (warp >= N_NODES) return;
    int d = warp;
    float ad = adst[d];

    float ee = leaky_exp(asrc[d] + ad);
    float4 hv = ((const float4*)(h + (size_t)d * 128))[lane];
    float ax = hv.x * ee, ay = hv.y * ee, az = hv.z * ee, aw = hv.w * ee;
    float denom = ee;

    int beg = rowptr[d], end = rowptr[d + 1];
    for (int j0 = beg; j0 < end; j0 += 32) {
        int idx = j0 + lane;
        int sj = 0;
        float aj = 0.f;
        if (idx < end) { sj = col[idx]; aj = asrc[sj]; }
        int cnt = min(32, end - j0);
#pragma unroll 4
        for (int j = 0; j < cnt; j++) {
            int s = __shfl_sync(0xffffffffu, sj, j);
            float a = __shfl_sync(0xffffffffu, aj, j);
            float w = leaky_exp(a + ad);
            float4 x = ((const float4*)(h + (size_t)s * 128))[lane];
            ax += w * x.x; ay += w * x.y; az += w * x.z; aw += w * x.w;
            denom += w;
        }
    }
    float inv = 1.f / denom;
    float4 b4 = ((const float4*)bias)[lane];
    float4 o;
    o.x = fmaxf(ax * inv + b4.x, 0.f);
    o.y = fmaxf(ay * inv + b4.y, 0.f);
    o.z = fmaxf(az * inv + b4.z, 0.f);
    o.w = fmaxf(aw * inv + b4.w, 0.f);
    ((float4*)(out + (size_t)d * 128))[lane] = o;
}

// ---------------- fused gather-aggregate layer 2 (C=64): softmax + bias + log_softmax ----------------
__global__ void agg2(const int* __restrict__ rowptr, const int* __restrict__ col,
                     const float* __restrict__ h, const float* __restrict__ asrc,
                     const float* __restrict__ adst, const float* __restrict__ bias,
                     float* __restrict__ out) {
    int warp = (blockIdx.x * blockDim.x + threadIdx.x) >> 5;
    int lane = threadIdx.x & 31;
    if (warp >= N_NODES) return;
    int d = warp;
    float ad = adst[d];

    float ee = leaky_exp(asrc[d] + ad);
    float2 hv = ((const float2*)(h + (size_t)d * 64))[lane];
    float ax = hv.x * ee, ay = hv.y * ee;
    float denom = ee;

    int beg = rowptr[d], end = rowptr[d + 1];
    for (int j0 = beg; j0 < end; j0 += 32) {
        int idx = j0 + lane;
        int sj = 0;
        float aj = 0.f;
        if (idx < end) { sj = col[idx]; aj = asrc[sj]; }
        int cnt = min(32, end - j0);
#pragma unroll 4
        for (int j = 0; j < cnt; j++) {
            int s = __shfl_sync(0xffffffffu, sj, j);
            float a = __shfl_sync(0xffffffffu, aj, j);
            float w = leaky_exp(a + ad);
            float2 x = ((const float2*)(h + (size_t)s * 64))[lane];
            ax += w * x.x; ay += w * x.y;
            denom += w;
        }
    }
    float inv = 1.f / denom;
    float2 b2 = ((const float2*)bias)[lane];
    float v0 = ax * inv + b2.x;
    float v1 = ay * inv + b2.y;
    float m = fmaxf(v0, v1);
#pragma unroll
    for (int o = 16; o > 0; o >>= 1) m = fmaxf(m, __shfl_xor_sync(0xffffffffu, m, o));
    float sm = __expf(v0 - m) + __expf(v1 - m);
#pragma unroll
    for (int o = 16; o > 0; o >>= 1) sm += __shfl_xor_sync(0xffffffffu, sm, o);
    float lse = m + logf(sm);
    float2 o2;
    o2.x = v0 - lse;
    o2.y = v1 - lse;
    ((float2*)(out + (size_t)d * 64))[lane] = o2;
}

// ---------------- host orchestration ----------------
extern "C" void kernel_launch(void* const* d_in, const int* in_sizes, int n_in,
                              void* d_out, int out_size) {
    const float* x   = (const float*)d_in[0];
    const void*  ei  = d_in[1];
    const float* W1  = (const float*)d_in[2];
    const float* as1 = (const float*)d_in[3];
    const float* ad1 = (const float*)d_in[4];
    const float* b1  = (const float*)d_in[5];
    const float* W2  = (const float*)d_in[6];
    const float* as2 = (const float*)d_in[7];
    const float* ad2 = (const float*)d_in[8];
    const float* b2  = (const float*)d_in[9];
    float* out = (float*)d_out;

    int E = in_sizes[1] / 2;

    float *h1, *hid, *h2, *asrc, *adst;
    int *cnt, *rowptr, *cur, *col, *bsum;
    cudaGetSymbolAddress((void**)&h1,  g_h1);
    cudaGetSymbolAddress((void**)&hid, g_hid);
    cudaGetSymbolAddress((void**)&h2,  g_h2);
    cudaGetSymbolAddress((void**)&asrc, g_asrc);
    cudaGetSymbolAddress((void**)&adst, g_adst);
    cudaGetSymbolAddress((void**)&cnt, g_cnt);
    cudaGetSymbolAddress((void**)&rowptr, g_rowptr);
    cudaGetSymbolAddress((void**)&cur, g_cur);
    cudaGetSymbolAddress((void**)&col, g_col);
    cudaGetSymbolAddress((void**)&bsum, g_bsum);

    const int nodeBlocks = (N_NODES + 255) / 256;
    const int nodeWarpBlocks = (N_NODES * 32 + 255) / 256;
    const int edgeBlocks = (E + 255) / 256;

    detect_idx_dtype<<<1, 1>>>((const int*)ei);

    // ---- CSR build (shared by both layers) ----
    zero_counts<<<nodeBlocks, 256>>>(cnt);
    count_edges<<<edgeBlocks, 256>>>(ei, E, cnt);
    scan_block<<<NUM_SCAN_BLOCKS, SCAN_CHUNK>>>(cnt, rowptr, bsum);
    scan_bsums<<<1, 128>>>(bsum);
    add_offsets<<<nodeBlocks, 256>>>(rowptr, bsum, cur, E);
    scatter_edges<<<edgeBlocks, 256>>>(ei, E, cur, col);

    // ===== Layer 1 =====
    {
        dim3 grid(1, (N_NODES + 127) / 128);
        tf32_gemm<128, 128, 32><<<grid, 256>>>(x, W1, h1, N_NODES, 128, 256);
    }
    node_dots<128><<<nodeWarpBlocks, 256>>>(h1, as1, ad1, asrc, adst);
    agg1<<<nodeWarpBlocks, 256>>>(rowptr, col, h1, asrc, adst, b1, hid);

    // ===== Layer 2 =====
    {
        dim3 grid(1, (N_NODES + 127) / 128);
        tf32_gemm<128, 64, 32><<<grid, 256>>>(hid, W2, h2, N_NODES, 64, 128);
    }
    node_dots<64><<<nodeWarpBlocks, 256>>>(h2, as2, ad2, asrc, adst);
    agg2<<<nodeWarpBlocks, 256>>>(rowptr, col, h2, asrc, adst, b2, out);
}

// round 8
// speedup vs baseline: 1.0745x; 1.0745x over previous
#include <cuda_runtime.h>
#include <cuda_bf16.h>
#include <math.h>
#include <stdint.h>

#define N_NODES 50000
#define NEG_SLOPE 0.2f
#define MAX_E 1200000
#define SCAN_CHUNK 512
#define NUM_SCAN_BLOCKS ((N_NODES + SCAN_CHUNK - 1) / SCAN_CHUNK)

// ---------------- device scratch (no allocs allowed) ----------------
__device__ float g_h1 [(size_t)N_NODES * 128];
__device__ float g_hid[(size_t)N_NODES * 128];
__device__ float g_h2 [(size_t)N_NODES * 64];
__device__ float g_asrc[N_NODES];
__device__ float g_adst[N_NODES];
__device__ int   g_cnt[N_NODES];
__device__ int   g_rowptr[N_NODES + 1];
__device__ int   g_cur[N_NODES];
__device__ int   g_col[MAX_E];
__device__ int   g_bsum[NUM_SCAN_BLOCKS + 1];
__device__ int   g_idx64;

__device__ __forceinline__ float leaky_exp(float e) {
    e = (e > 0.f) ? e : NEG_SLOPE * e;
    return __expf(e);
}

// ---------------- dtype detection for edge_index (int32 vs int64) ----------------
__global__ void detect_idx_dtype(const int* __restrict__ ei32) {
    int z = 1;
    for (int i = 1; i < 256; i += 2)
        if (ei32[i] != 0) { z = 0; break; }
    g_idx64 = z;
}

// ---------------- CSR build ----------------
__global__ void zero_counts(int* __restrict__ cnt) {
    int i = blockIdx.x * blockDim.x + threadIdx.x;
    if (i < N_NODES) cnt[i] = 0;
}

__global__ void count_edges(const void* __restrict__ ei, int E, int* __restrict__ cnt) {
    int i = blockIdx.x * blockDim.x + threadIdx.x;
    if (i >= E) return;
    int d;
    if (g_idx64) d = (int)((const long long*)ei)[(size_t)E + i];
    else         d = ((const int*)ei)[E + i];
    atomicAdd(cnt + d, 1);
}

__global__ void scan_block(const int* __restrict__ cnt, int* __restrict__ rowptr,
                           int* __restrict__ bsum) {
    __shared__ int sm[SCAN_CHUNK];
    int b = blockIdx.x, t = threadIdx.x;
    int i = b * SCAN_CHUNK + t;
    int v = (i < N_NODES) ? cnt[i] : 0;
    sm[t] = v;
    __syncthreads();
#pragma unroll
    for (int o = 1; o < SCAN_CHUNK; o <<= 1) {
        int x = (t >= o) ? sm[t - o] : 0;
        __syncthreads();
        sm[t] += x;
        __syncthreads();
    }
    if (i < N_NODES) rowptr[i] = sm[t] - v;  // exclusive
    if (t == SCAN_CHUNK - 1) bsum[b] = sm[t];
}

__global__ void scan_bsums(int* __restrict__ bsum) {
    __shared__ int sm[NUM_SCAN_BLOCKS];
    int t = threadIdx.x;
    if (t < NUM_SCAN_BLOCKS) sm[t] = bsum[t];
    __syncthreads();
    if (t == 0) {
        int acc = 0;
        for (int i = 0; i < NUM_SCAN_BLOCKS; i++) { int v = sm[i]; sm[i] = acc; acc += v; }
    }
    __syncthreads();
    if (t < NUM_SCAN_BLOCKS) bsum[t] = sm[t];
}

__global__ void add_offsets(int* __restrict__ rowptr, const int* __restrict__ bsum,
                            int* __restrict__ cur, int E) {
    int i = blockIdx.x * blockDim.x + threadIdx.x;
    if (i < N_NODES) {
        int r = rowptr[i] + bsum[i / SCAN_CHUNK];
        rowptr[i] = r;
        cur[i] = r;
    }
    if (i == 0) rowptr[N_NODES] = E;
}

__global__ void scatter_edges(const void* __restrict__ ei, int E,
                              int* __restrict__ cur, int* __restrict__ col) {
    int i = blockIdx.x * blockDim.x + threadIdx.x;
    if (i >= E) return;
    int s, d;
    if (g_idx64) {
        const long long* p = (const long long*)ei;
        s = (int)p[i];
        d = (int)p[(size_t)E + i];
    } else {
        const int* p = (const int*)ei;
        s = p[i];
        d = p[E + i];
    }
    int pos = atomicAdd(cur + d, 1);
    col[pos] = s;
}

// ---------------- bf16 3-term split tensor-core GEMM (m16n8k16) ----------------
// v = big + sml exactly at bf16 precision of each; product uses big*big + big*sml + sml*big.
__device__ __forceinline__ void split_pack(float v0, float v1, uint32_t& big, uint32_t& sml) {
    __nv_bfloat162 b2 = __floats2bfloat162_rn(v0, v1);   // .x = v0 (low), .y = v1 (high)
    float2 f2 = __bfloat1622float2(b2);
    __nv_bfloat162 s2 = __floats2bfloat162_rn(v0 - f2.x, v1 - f2.y);
    big = *reinterpret_cast<uint32_t*>(&b2);
    sml = *reinterpret_cast<uint32_t*>(&s2);
}

__device__ __forceinline__ void mma_bf16(float* c, const uint32_t* a, const uint32_t* b) {
    asm volatile(
        "mma.sync.aligned.m16n8k16.row.col.f32.bf16.bf16.f32 "
        "{%0,%1,%2,%3}, {%4,%5,%6,%7}, {%8,%9}, {%0,%1,%2,%3};"
        : "+f"(c[0]), "+f"(c[1]), "+f"(c[2]), "+f"(c[3])
        : "r"(a[0]), "r"(a[1]), "r"(a[2]), "r"(a[3]), "r"(b[0]), "r"(b[1]));
}

// A [M,K] row-major, B [K,N] row-major, C [M,N]. K%BK==0, BN==N (single block col).
// 8 warps (256 thr), warp grid 4x2, warp tile 32 x (BN/2).
template <int BM, int BN, int BK>
__global__ void bf16_gemm(const float* __restrict__ A, const float* __restrict__ B,
                          float* __restrict__ C, int M, int N, int K) {
    constexpr int WR = 4, WC = 2;
    constexpr int nThreads = WR * WC * 32;
    constexpr int WM = BM / WR;          // 32
    constexpr int WN = BN / WC;          // 64 or 32
    constexpr int MT = WM / 16;          // 2
    constexpr int NT = WN / 8;           // 8 or 4
    constexpr int KS = BK / 16;          // 2
    constexpr int APAD = 4, BPAD = 8;

    __shared__ float As[BM][BK + APAD];
    __shared__ float Bs[BK][BN + BPAD];

    int tid = threadIdx.x;
    int wid = tid >> 5;
    int lane = tid & 31;
    int wr = wid / WC, wc = wid % WC;
    int row0 = blockIdx.y * BM;
    int grp = lane >> 2;          // 0..7
    int qd  = lane & 3;           // 0..3

    float acc[MT][NT][4];
#pragma unroll
    for (int i = 0; i < MT; i++)
#pragma unroll
        for (int j = 0; j < NT; j++)
#pragma unroll
            for (int q = 0; q < 4; q++) acc[i][j][q] = 0.f;

    for (int k0 = 0; k0 < K; k0 += BK) {
        // A tile: BM x BK via float4
#pragma unroll
        for (int i = tid; i < BM * BK / 4; i += nThreads) {
            int r = i / (BK / 4);
            int c4 = i % (BK / 4);
            int gr = row0 + r;
            float4 v = make_float4(0.f, 0.f, 0.f, 0.f);
            if (gr < M) v = *(const float4*)(A + (size_t)gr * K + k0 + c4 * 4);
            *(float4*)&As[r][c4 * 4] = v;
        }
        // B tile: BK x BN via float4
#pragma unroll
        for (int i = tid; i < BK * BN / 4; i += nThreads) {
            int r = i / (BN / 4);
            int c4 = i % (BN / 4);
            *(float4*)&Bs[r][c4 * 4] = *(const float4*)(B + (size_t)(k0 + r) * N + c4 * 4);
        }
        __syncthreads();

#pragma unroll
        for (int ks = 0; ks < KS; ks++) {
            int kc = ks * 16 + qd * 2;
            // A fragments (row-major 16x16): regs 0/1 = cols kc..kc+1, rows gr / gr+8;
            // regs 2/3 = cols kc+8..kc+9
            uint32_t abig[MT][4], asml[MT][4];
#pragma unroll
            for (int mt = 0; mt < MT; mt++) {
                int rb = wr * WM + mt * 16 + grp;
                split_pack(As[rb][kc],         As[rb][kc + 1],     abig[mt][0], asml[mt][0]);
                split_pack(As[rb + 8][kc],     As[rb + 8][kc + 1], abig[mt][1], asml[mt][1]);
                split_pack(As[rb][kc + 8],     As[rb][kc + 9],     abig[mt][2], asml[mt][2]);
                split_pack(As[rb + 8][kc + 8], As[rb + 8][kc + 9], abig[mt][3], asml[mt][3]);
            }
#pragma unroll
            for (int nt = 0; nt < NT; nt++) {
                int n = wc * WN + nt * 8 + grp;
                int kb = ks * 16 + qd * 2;
                uint32_t bbig[2], bsml[2];
                split_pack(Bs[kb][n],     Bs[kb + 1][n], bbig[0], bsml[0]);
                split_pack(Bs[kb + 8][n], Bs[kb + 9][n], bbig[1], bsml[1]);
#pragma unroll
                for (int mt = 0; mt < MT; mt++) {
                    mma_bf16(acc[mt][nt], abig[mt], bbig);
                    mma_bf16(acc[mt][nt], abig[mt], bsml);
                    mma_bf16(acc[mt][nt], asml[mt], bbig);
                }
            }
        }
        __syncthreads();
    }

    // epilogue
#pragma unroll
    for (int mt = 0; mt < MT; mt++) {
#pragma unroll
        for (int nt = 0; nt < NT; nt++) {
            int row = row0 + wr * WM + mt * 16 + grp;
            int col = wc * WN + nt * 8 + qd * 2;
            if (row < M)
                *(float2*)(C + (size_t)row * N + col) =
                    make_float2(acc[mt][nt][0], acc[mt][nt][1]);
            if (row + 8 < M)
                *(float2*)(C + (size_t)(row + 8) * N + col) =
                    make_float2(acc[mt][nt][2], acc[mt][nt][3]);
        }
    }
}

// ---------------- per-node attention dots ----------------
template <int C>
__global__ void node_dots(const float* __restrict__ h,
                          const float* __restrict__ att_s, const float* __restrict__ att_d,
                          float* __restrict__ asrc, float* __restrict__ adst) {
    int warp = (blockIdx.x * blockDim.x + threadIdx.x) >> 5;
    int lane = threadIdx.x & 31;
    if (warp >= N_NODES) return;
    float ss = 0.f, sd = 0.f;
    const float* hrow = h + (size_t)warp * C;
#pragma unroll
    for (int j = lane; j < C; j += 32) {
        float v = hrow[j];
        ss += v * att_s[j];
        sd += v * att_d[j];
    }
#pragma unroll
    for (int o = 16; o > 0; o >>= 1) {
        ss += __shfl_down_sync(0xffffffffu, ss, o);
        sd += __shfl_down_sync(0xffffffffu, sd, o);
    }
    if (lane == 0) {
        asrc[warp] = ss;
        adst[warp] = sd;
    }
}

// ---------------- fused gather-aggregate layer 1 (C=128): softmax + bias + ReLU ----------------
__global__ void agg1(const int* __restrict__ rowptr, const int* __restrict__ col,
                     const float* __restrict__ h, const float* __restrict__ asrc,
                     const float* __restrict__ adst, const float* __restrict__ bias,
                     float* __restrict__ out) {
    int warp = (blockIdx.x * blockDim.x + threadIdx.x) >> 5;
    int lane = threadIdx.x & 31;
    if (warp >= N_NODES) return;
    int d = warp;
    float ad = adst[d];

    float ee = leaky_exp(asrc[d] + ad);
    float4 hv = ((const float4*)(h + (size_t)d * 128))[lane];
    float ax = hv.x * ee, ay = hv.y * ee, az = hv.z * ee, aw = hv.w * ee;
    float denom = ee;

    int beg = rowptr[d], end = rowptr[d + 1];
    for (int j0 = beg; j0 < end; j0 += 32) {
        int idx = j0 + lane;
        int sj = 0;
        float aj = 0.f;
        if (idx < end) { sj = col[idx]; aj = asrc[sj]; }
        int cnt = min(32, end - j0);
#pragma unroll 4
        for (int j = 0; j < cnt; j++) {
            int s = __shfl_sync(0xffffffffu, sj, j);
            float a = __shfl_sync(0xffffffffu, aj, j);
            float w = leaky_exp(a + ad);
            float4 x = ((const float4*)(h + (size_t)s * 128))[lane];
            ax += w * x.x; ay += w * x.y; az += w * x.z; aw += w * x.w;
            denom += w;
        }
    }
    float inv = 1.f / denom;
    float4 b4 = ((const float4*)bias)[lane];
    float4 o;
    o.x = fmaxf(ax * inv + b4.x, 0.f);
    o.y = fmaxf(ay * inv + b4.y, 0.f);
    o.z = fmaxf(az * inv + b4.z, 0.f);
    o.w = fmaxf(aw * inv + b4.w, 0.f);
    ((float4*)(out + (size_t)d * 128))[lane] = o;
}

// ---------------- fused gather-aggregate layer 2 (C=64): softmax + bias + log_softmax ----------------
__global__ void agg2(const int* __restrict__ rowptr, const int* __restrict__ col,
                     const float* __restrict__ h, const float* __restrict__ asrc,
                     const float* __restrict__ adst, const float* __restrict__ bias,
                     float* __restrict__ out) {
    int warp = (blockIdx.x * blockDim.x + threadIdx.x) >> 5;
    int lane = threadIdx.x & 31;
    if (warp >= N_NODES) return;
    int d = warp;
    float ad = adst[d];

    float ee = leaky_exp(asrc[d] + ad);
    float2 hv = ((const float2*)(h + (size_t)d * 64))[lane];
    float ax = hv.x * ee, ay = hv.y * ee;
    float denom = ee;

    int beg = rowptr[d], end = rowptr[d + 1];
    for (int j0 = beg; j0 < end; j0 += 32) {
        int idx = j0 + lane;
        int sj = 0;
        float aj = 0.f;
        if (idx < end) { sj = col[idx]; aj = asrc[sj]; }
        int cnt = min(32, end - j0);
#pragma unroll 4
        for (int j = 0; j < cnt; j++) {
            int s = __shfl_sync(0xffffffffu, sj, j);
            float a = __shfl_sync(0xffffffffu, aj, j);
            float w = leaky_exp(a + ad);
            float2 x = ((const float2*)(h + (size_t)s * 64))[lane];
            ax += w * x.x; ay += w * x.y;
            denom += w;
        }
    }
    float inv = 1.f / denom;
    float2 b2 = ((const float2*)bias)[lane];
    float v0 = ax * inv + b2.x;
    float v1 = ay * inv + b2.y;
    float m = fmaxf(v0, v1);
#pragma unroll
    for (int o = 16; o > 0; o >>= 1) m = fmaxf(m, __shfl_xor_sync(0xffffffffu, m, o));
    float sm = __expf(v0 - m) + __expf(v1 - m);
#pragma unroll
    for (int o = 16; o > 0; o >>= 1) sm += __shfl_xor_sync(0xffffffffu, sm, o);
    float lse = m + logf(sm);
    float2 o2;
    o2.x = v0 - lse;
    o2.y = v1 - lse;
    ((float2*)(out + (size_t)d * 64))[lane] = o2;
}

// ---------------- host orchestration ----------------
extern "C" void kernel_launch(void* const* d_in, const int* in_sizes, int n_in,
                              void* d_out, int out_size) {
    const float* x   = (const float*)d_in[0];
    const void*  ei  = d_in[1];
    const float* W1  = (const float*)d_in[2];
    const float* as1 = (const float*)d_in[3];
    const float* ad1 = (const float*)d_in[4];
    const float* b1  = (const float*)d_in[5];
    const float* W2  = (const float*)d_in[6];
    const float* as2 = (const float*)d_in[7];
    const float* ad2 = (const float*)d_in[8];
    const float* b2  = (const float*)d_in[9];
    float* out = (float*)d_out;

    int E = in_sizes[1] / 2;

    float *h1, *hid, *h2, *asrc, *adst;
    int *cnt, *rowptr, *cur, *col, *bsum;
    cudaGetSymbolAddress((void**)&h1,  g_h1);
    cudaGetSymbolAddress((void**)&hid, g_hid);
    cudaGetSymbolAddress((void**)&h2,  g_h2);
    cudaGetSymbolAddress((void**)&asrc, g_asrc);
    cudaGetSymbolAddress((void**)&adst, g_adst);
    cudaGetSymbolAddress((void**)&cnt, g_cnt);
    cudaGetSymbolAddress((void**)&rowptr, g_rowptr);
    cudaGetSymbolAddress((void**)&cur, g_cur);
    cudaGetSymbolAddress((void**)&col, g_col);
    cudaGetSymbolAddress((void**)&bsum, g_bsum);

    const int nodeBlocks = (N_NODES + 255) / 256;
    const int nodeWarpBlocks = (N_NODES * 32 + 255) / 256;
    const int edgeBlocks = (E + 255) / 256;

    detect_idx_dtype<<<1, 1>>>((const int*)ei);

    // ---- CSR build (shared by both layers) ----
    zero_counts<<<nodeBlocks, 256>>>(cnt);
    count_edges<<<edgeBlocks, 256>>>(ei, E, cnt);
    scan_block<<<NUM_SCAN_BLOCKS, SCAN_CHUNK>>>(cnt, rowptr, bsum);
    scan_bsums<<<1, 128>>>(bsum);
    add_offsets<<<nodeBlocks, 256>>>(rowptr, bsum, cur, E);
    scatter_edges<<<edgeBlocks, 256>>>(ei, E, cur, col);

    // ===== Layer 1 =====
    {
        dim3 grid(1, (N_NODES + 127) / 128);
        bf16_gemm<128, 128, 32><<<grid, 256>>>(x, W1, h1, N_NODES, 128, 256);
    }
    node_dots<128><<<nodeWarpBlocks, 256>>>(h1, as1, ad1, asrc, adst);
    agg1<<<nodeWarpBlocks, 256>>>(rowptr, col, h1, asrc, adst, b1, hid);

    // ===== Layer 2 =====
    {
        dim3 grid(1, (N_NODES + 127) / 128);
        bf16_gemm<128, 64, 32><<<grid, 256>>>(hid, W2, h2, N_NODES, 64, 128);
    }
    node_dots<64><<<nodeWarpBlocks, 256>>>(h2, as2, ad2, asrc, adst);
    agg2<<<nodeWarpBlocks, 256>>>(rowptr, col, h2, asrc, adst, b2, out);
}

// round 11
// speedup vs baseline: 1.2229x; 1.1381x over previous
#include <cuda_runtime.h>
#include <cuda_bf16.h>
#include <math.h>
#include <stdint.h>

#define N_NODES 50000
#define NEG_SLOPE 0.2f
#define MAX_E 1200000
#define SCAN_CHUNK 512
#define NUM_SCAN_BLOCKS ((N_NODES + SCAN_CHUNK - 1) / SCAN_CHUNK)

// ---------------- device scratch (no allocs allowed) ----------------
__device__ float g_h1 [(size_t)N_NODES * 128];
__device__ float g_hid[(size_t)N_NODES * 128];
__device__ float g_h2 [(size_t)N_NODES * 64];
__device__ float g_asrc[N_NODES];
__device__ float g_adst[N_NODES];
__device__ int   g_cnt[N_NODES];
__device__ int   g_rowptr[N_NODES + 1];
__device__ int   g_cur[N_NODES];
__device__ int   g_col[MAX_E];
__device__ int   g_bsum[NUM_SCAN_BLOCKS + 1];
__device__ int   g_idx64;

__device__ __forceinline__ float leaky_exp(float e) {
    e = (e > 0.f) ? e : NEG_SLOPE * e;
    return __expf(e);
}

// ---------------- dtype detection for edge_index (int32 vs int64) ----------------
__global__ void detect_idx_dtype(const int* __restrict__ ei32) {
    int z = 1;
    for (int i = 1; i < 256; i += 2)
        if (ei32[i] != 0) { z = 0; break; }
    g_idx64 = z;
}

// ---------------- zero attention-dot accumulators ----------------
__global__ void zero_dots(float* __restrict__ asrc, float* __restrict__ adst) {
    int i = blockIdx.x * blockDim.x + threadIdx.x;
    if (i < N_NODES) { asrc[i] = 0.f; adst[i] = 0.f; }
}

// ---------------- CSR build ----------------
__global__ void zero_counts(int* __restrict__ cnt) {
    int i = blockIdx.x * blockDim.x + threadIdx.x;
    if (i < N_NODES) cnt[i] = 0;
}

__global__ void count_edges(const void* __restrict__ ei, int E, int* __restrict__ cnt) {
    int i = blockIdx.x * blockDim.x + threadIdx.x;
    if (i >= E) return;
    int d;
    if (g_idx64) d = (int)((const long long*)ei)[(size_t)E + i];
    else         d = ((const int*)ei)[E + i];
    atomicAdd(cnt + d, 1);
}

__global__ void scan_block(const int* __restrict__ cnt, int* __restrict__ rowptr,
                           int* __restrict__ bsum) {
    __shared__ int sm[SCAN_CHUNK];
    int b = blockIdx.x, t = threadIdx.x;
    int i = b * SCAN_CHUNK + t;
    int v = (i < N_NODES) ? cnt[i] : 0;
    sm[t] = v;
    __syncthreads();
#pragma unroll
    for (int o = 1; o < SCAN_CHUNK; o <<= 1) {
        int x = (t >= o) ? sm[t - o] : 0;
        __syncthreads();
        sm[t] += x;
        __syncthreads();
    }
    if (i < N_NODES) rowptr[i] = sm[t] - v;  // exclusive
    if (t == SCAN_CHUNK - 1) bsum[b] = sm[t];
}

__global__ void scan_bsums(int* __restrict__ bsum) {
    __shared__ int sm[NUM_SCAN_BLOCKS];
    int t = threadIdx.x;
    if (t < NUM_SCAN_BLOCKS) sm[t] = bsum[t];
    __syncthreads();
    if (t == 0) {
        int acc = 0;
        for (int i = 0; i < NUM_SCAN_BLOCKS; i++) { int v = sm[i]; sm[i] = acc; acc += v; }
    }
    __syncthreads();
    if (t < NUM_SCAN_BLOCKS) bsum[t] = sm[t];
}

__global__ void add_offsets(int* __restrict__ rowptr, const int* __restrict__ bsum,
                            int* __restrict__ cur, int E) {
    int i = blockIdx.x * blockDim.x + threadIdx.x;
    if (i < N_NODES) {
        int r = rowptr[i] + bsum[i / SCAN_CHUNK];
        rowptr[i] = r;
        cur[i] = r;
    }
    if (i == 0) rowptr[N_NODES] = E;
}

__global__ void scatter_edges(const void* __restrict__ ei, int E,
                              int* __restrict__ cur, int* __restrict__ col) {
    int i = blockIdx.x * blockDim.x + threadIdx.x;
    if (i >= E) return;
    int s, d;
    if (g_idx64) {
        const long long* p = (const long long*)ei;
        s = (int)p[i];
        d = (int)p[(size_t)E + i];
    } else {
        const int* p = (const int*)ei;
        s = p[i];
        d = p[E + i];
    }
    int pos = atomicAdd(cur + d, 1);
    col[pos] = s;
}

// ---------------- bf16 3-term split tensor-core GEMM (m16n8k16) + fused attention dots ----------------
__device__ __forceinline__ void split_pack(float v0, float v1, uint32_t& big, uint32_t& sml) {
    __nv_bfloat162 b2 = __floats2bfloat162_rn(v0, v1);
    float2 f2 = __bfloat1622float2(b2);
    __nv_bfloat162 s2 = __floats2bfloat162_rn(v0 - f2.x, v1 - f2.y);
    big = *reinterpret_cast<uint32_t*>(&b2);
    sml = *reinterpret_cast<uint32_t*>(&s2);
}

__device__ __forceinline__ void mma_bf16(float* c, const uint32_t* a, const uint32_t* b) {
    asm volatile(
        "mma.sync.aligned.m16n8k16.row.col.f32.bf16.bf16.f32 "
        "{%0,%1,%2,%3}, {%4,%5,%6,%7}, {%8,%9}, {%0,%1,%2,%3};"
        : "+f"(c[0]), "+f"(c[1]), "+f"(c[2]), "+f"(c[3])
        : "r"(a[0]), "r"(a[1]), "r"(a[2]), "r"(a[3]), "r"(b[0]), "r"(b[1]));
}

// A [M,K] row-major, B [K,N] row-major, C [M,N]. K%BK==0, BN==N (single block col).
// 8 warps, warp grid 4x2. Epilogue also accumulates asrc/adst = C·att_s / C·att_d per row.
template <int BM, int BN, int BK>
__global__ void bf16_gemm_dots(const float* __restrict__ A, const float* __restrict__ B,
                               float* __restrict__ C,
                               const float* __restrict__ att_s, const float* __restrict__ att_d,
                               float* __restrict__ asrc, float* __restrict__ adst,
                               int M, int N, int K) {
    constexpr int WR = 4, WC = 2;
    constexpr int nThreads = WR * WC * 32;
    constexpr int WM = BM / WR;          // 32
    constexpr int WN = BN / WC;          // 64 or 32
    constexpr int MT = WM / 16;          // 2
    constexpr int NT = WN / 8;           // 8 or 4
    constexpr int KS = BK / 16;          // 2
    constexpr int APAD = 4, BPAD = 8;

    __shared__ float As[BM][BK + APAD];
    __shared__ float Bs[BK][BN + BPAD];

    int tid = threadIdx.x;
    int wid = tid >> 5;
    int lane = tid & 31;
    int wr = wid / WC, wc = wid % WC;
    int row0 = blockIdx.y * BM;
    int grp = lane >> 2;          // 0..7
    int qd  = lane & 3;           // 0..3

    float acc[MT][NT][4];
#pragma unroll
    for (int i = 0; i < MT; i++)
#pragma unroll
        for (int j = 0; j < NT; j++)
#pragma unroll
            for (int q = 0; q < 4; q++) acc[i][j][q] = 0.f;

    for (int k0 = 0; k0 < K; k0 += BK) {
#pragma unroll
        for (int i = tid; i < BM * BK / 4; i += nThreads) {
            int r = i / (BK / 4);
            int c4 = i % (BK / 4);
            int gr = row0 + r;
            float4 v = make_float4(0.f, 0.f, 0.f, 0.f);
            if (gr < M) v = *(const float4*)(A + (size_t)gr * K + k0 + c4 * 4);
            *(float4*)&As[r][c4 * 4] = v;
        }
#pragma unroll
        for (int i = tid; i < BK * BN / 4; i += nThreads) {
            int r = i / (BN / 4);
            int c4 = i % (BN / 4);
            *(float4*)&Bs[r][c4 * 4] = *(const float4*)(B + (size_t)(k0 + r) * N + c4 * 4);
        }
        __syncthreads();

#pragma unroll
        for (int ks = 0; ks < KS; ks++) {
            int kc = ks * 16 + qd * 2;
            uint32_t abig[MT][4], asml[MT][4];
#pragma unroll
            for (int mt = 0; mt < MT; mt++) {
                int rb = wr * WM + mt * 16 + grp;
                split_pack(As[rb][kc],         As[rb][kc + 1],     abig[mt][0], asml[mt][0]);
                split_pack(As[rb + 8][kc],     As[rb + 8][kc + 1], abig[mt][1], asml[mt][1]);
                split_pack(As[rb][kc + 8],     As[rb][kc + 9],     abig[mt][2], asml[mt][2]);
                split_pack(As[rb + 8][kc + 8], As[rb + 8][kc + 9], abig[mt][3], asml[mt][3]);
            }
#pragma unroll
            for (int nt = 0; nt < NT; nt++) {
                int n = wc * WN + nt * 8 + grp;
                int kb = ks * 16 + qd * 2;
                uint32_t bbig[2], bsml[2];
                split_pack(Bs[kb][n],     Bs[kb + 1][n], bbig[0], bsml[0]);
                split_pack(Bs[kb + 8][n], Bs[kb + 9][n], bbig[1], bsml[1]);
#pragma unroll
                for (int mt = 0; mt < MT; mt++) {
                    mma_bf16(acc[mt][nt], abig[mt], bbig);
                    mma_bf16(acc[mt][nt], abig[mt], bsml);
                    mma_bf16(acc[mt][nt], asml[mt], bbig);
                }
            }
        }
        __syncthreads();
    }

    // ---- epilogue: store C + fused per-row attention dots ----
    float ss[MT][2], sd[MT][2];
#pragma unroll
    for (int mt = 0; mt < MT; mt++) { ss[mt][0] = ss[mt][1] = sd[mt][0] = sd[mt][1] = 0.f; }

#pragma unroll
    for (int mt = 0; mt < MT; mt++) {
#pragma unroll
        for (int nt = 0; nt < NT; nt++) {
            int row = row0 + wr * WM + mt * 16 + grp;
            int col = wc * WN + nt * 8 + qd * 2;
            if (row < M)
                *(float2*)(C + (size_t)row * N + col) =
                    make_float2(acc[mt][nt][0], acc[mt][nt][1]);
            if (row + 8 < M)
                *(float2*)(C + (size_t)(row + 8) * N + col) =
                    make_float2(acc[mt][nt][2], acc[mt][nt][3]);

            float a0 = att_s[col], a1 = att_s[col + 1];
            float d0 = att_d[col], d1 = att_d[col + 1];
            ss[mt][0] += acc[mt][nt][0] * a0 + acc[mt][nt][1] * a1;
            ss[mt][1] += acc[mt][nt][2] * a0 + acc[mt][nt][3] * a1;
            sd[mt][0] += acc[mt][nt][0] * d0 + acc[mt][nt][1] * d1;
            sd[mt][1] += acc[mt][nt][2] * d0 + acc[mt][nt][3] * d1;
        }
    }
    // reduce over the 4 lanes of each quad (qd), then one atomicAdd per row-half
#pragma unroll
    for (int mt = 0; mt < MT; mt++) {
#pragma unroll
        for (int h = 0; h < 2; h++) {
            float vs = ss[mt][h], vd = sd[mt][h];
            vs += __shfl_xor_sync(0xffffffffu, vs, 1);
            vs += __shfl_xor_sync(0xffffffffu, vs, 2);
            vd += __shfl_xor_sync(0xffffffffu, vd, 1);
            vd += __shfl_xor_sync(0xffffffffu, vd, 2);
            if (qd == 0) {
                int row = row0 + wr * WM + mt * 16 + grp + h * 8;
                if (row < M) {
                    atomicAdd(asrc + row, vs);
                    atomicAdd(adst + row, vd);
                }
            }
        }
    }
}

// ---------------- fused gather-aggregate layer 1 (C=128): softmax + bias + ReLU ----------------
__global__ void agg1(const int* __restrict__ rowptr, const int* __restrict__ col,
                     const float* __restrict__ h, const float* __restrict__ asrc,
                     const float* __restrict__ adst, const float* __restrict__ bias,
                     float* __restrict__ out) {
    int warp = (blockIdx.x * blockDim.x + threadIdx.x) >> 5;
    int lane = threadIdx.x & 31;
    if (warp >= N_NODES) return;
    int d = warp;
    float ad = adst[d];

    float ee = leaky_exp(asrc[d] + ad);
    float4 hv = ((const float4*)(h + (size_t)d * 128))[lane];
    float ax = hv.x * ee, ay = hv.y * ee, az = hv.z * ee, aw = hv.w * ee;
    float denom = ee;

    int beg = rowptr[d], end = rowptr[d + 1];
    for (int j0 = beg; j0 < end; j0 += 32) {
        int idx = j0 + lane;
        int sj = 0;
        float aj = 0.f;
        if (idx < end) { sj = col[idx]; aj = asrc[sj]; }
        int cnt = min(32, end - j0);
#pragma unroll 4
        for (int j = 0; j < cnt; j++) {
            int s = __shfl_sync(0xffffffffu, sj, j);
            float a = __shfl_sync(0xffffffffu, aj, j);
            float w = leaky_exp(a + ad);
            float4 x = ((const float4*)(h + (size_t)s * 128))[lane];
            ax += w * x.x; ay += w * x.y; az += w * x.z; aw += w * x.w;
            denom += w;
        }
    }
    float inv = 1.f / denom;
    float4 b4 = ((const float4*)bias)[lane];
    float4 o;
    o.x = fmaxf(ax * inv + b4.x, 0.f);
    o.y = fmaxf(ay * inv + b4.y, 0.f);
    o.z = fmaxf(az * inv + b4.z, 0.f);
    o.w = fmaxf(aw * inv + b4.w, 0.f);
    ((float4*)(out + (size_t)d * 128))[lane] = o;
}

// ---------------- fused gather-aggregate layer 2 (C=64): softmax + bias + log_softmax ----------------
__global__ void agg2(const int* __restrict__ rowptr, const int* __restrict__ col,
                     const float* __restrict__ h, const float* __restrict__ asrc,
                     const float* __restrict__ adst, const float* __restrict__ bias,
                     float* __restrict__ out) {
    int warp = (blockIdx.x * blockDim.x + threadIdx.x) >> 5;
    int lane = threadIdx.x & 31;
    if (warp >= N_NODES) return;
    int d = warp;
    float ad = adst[d];

    float ee = leaky_exp(asrc[d] + ad);
    float2 hv = ((const float2*)(h + (size_t)d * 64))[lane];
    float ax = hv.x * ee, ay = hv.y * ee;
    float denom = ee;

    int beg = rowptr[d], end = rowptr[d + 1];
    for (int j0 = beg; j0 < end; j0 += 32) {
        int idx = j0 + lane;
        int sj = 0;
        float aj = 0.f;
        if (idx < end) { sj = col[idx]; aj = asrc[sj]; }
        int cnt = min(32, end - j0);
#pragma unroll 4
        for (int j = 0; j < cnt; j++) {
            int s = __shfl_sync(0xffffffffu, sj, j);
            float a = __shfl_sync(0xffffffffu, aj, j);
            float w = leaky_exp(a + ad);
            float2 x = ((const float2*)(h + (size_t)s * 64))[lane];
            ax += w * x.x; ay += w * x.y;
            denom += w;
        }
    }
    float inv = 1.f / denom;
    float2 b2 = ((const float2*)bias)[lane];
    float v0 = ax * inv + b2.x;
    float v1 = ay * inv + b2.y;
    float m = fmaxf(v0, v1);
#pragma unroll
    for (int o = 16; o > 0; o >>= 1) m = fmaxf(m, __shfl_xor_sync(0xffffffffu, m, o));
    float sm = __expf(v0 - m) + __expf(v1 - m);
#pragma unroll
    for (int o = 16; o > 0; o >>= 1) sm += __shfl_xor_sync(0xffffffffu, sm, o);
    float lse = m + logf(sm);
    float2 o2;
    o2.x = v0 - lse;
    o2.y = v1 - lse;
    ((float2*)(out + (size_t)d * 64))[lane] = o2;
}

// ---------------- host orchestration ----------------
extern "C" void kernel_launch(void* const* d_in, const int* in_sizes, int n_in,
                              void* d_out, int out_size) {
    const float* x   = (const float*)d_in[0];
    const void*  ei  = d_in[1];
    const float* W1  = (const float*)d_in[2];
    const float* as1 = (const float*)d_in[3];
    const float* ad1 = (const float*)d_in[4];
    const float* b1  = (const float*)d_in[5];
    const float* W2  = (const float*)d_in[6];
    const float* as2 = (const float*)d_in[7];
    const float* ad2 = (const float*)d_in[8];
    const float* b2  = (const float*)d_in[9];
    float* out = (float*)d_out;

    int E = in_sizes[1] / 2;

    float *h1, *hid, *h2, *asrc, *adst;
    int *cnt, *rowptr, *cur, *col, *bsum;
    cudaGetSymbolAddress((void**)&h1,  g_h1);
    cudaGetSymbolAddress((void**)&hid, g_hid);
    cudaGetSymbolAddress((void**)&h2,  g_h2);
    cudaGetSymbolAddress((void**)&asrc, g_asrc);
    cudaGetSymbolAddress((void**)&adst, g_adst);
    cudaGetSymbolAddress((void**)&cnt, g_cnt);
    cudaGetSymbolAddress((void**)&rowptr, g_rowptr);
    cudaGetSymbolAddress((void**)&cur, g_cur);
    cudaGetSymbolAddress((void**)&col, g_col);
    cudaGetSymbolAddress((void**)&bsum, g_bsum);

    // one-time handle creation (host-side only; no device memory involved)
    static cudaStream_t s_side = nullptr;
    static cudaEvent_t ev_fork = nullptr, ev_join = nullptr;
    if (!s_side) {
        cudaStreamCreateWithFlags(&s_side, cudaStreamNonBlocking);
        cudaEventCreateWithFlags(&ev_fork, cudaEventDisableTiming);
        cudaEventCreateWithFlags(&ev_join, cudaEventDisableTiming);
    }

    const int nodeBlocks = (N_NODES + 255) / 256;
    const int nodeWarpBlocks = (N_NODES * 32 + 255) / 256;
    const int edgeBlocks = (E + 255) / 256;

    // ---- prologue on main stream ----
    detect_idx_dtype<<<1, 1>>>((const int*)ei);
    zero_dots<<<nodeBlocks, 256>>>(asrc, adst);

    // ---- fork: CSR build on side stream, concurrent with layer-1 GEMM ----
    cudaEventRecord(ev_fork, 0);
    cudaStreamWaitEvent(s_side, ev_fork, 0);

    zero_counts<<<nodeBlocks, 256, 0, s_side>>>(cnt);
    count_edges<<<edgeBlocks, 256, 0, s_side>>>(ei, E, cnt);
    scan_block<<<NUM_SCAN_BLOCKS, SCAN_CHUNK, 0, s_side>>>(cnt, rowptr, bsum);
    scan_bsums<<<1, 128, 0, s_side>>>(bsum);
    add_offsets<<<nodeBlocks, 256, 0, s_side>>>(rowptr, bsum, cur, E);
    scatter_edges<<<edgeBlocks, 256, 0, s_side>>>(ei, E, cur, col);
    cudaEventRecord(ev_join, s_side);

    // ---- main stream: layer-1 GEMM with fused dots ----
    {
        dim3 grid(1, (N_NODES + 127) / 128);
        bf16_gemm_dots<128, 128, 32><<<grid, 256>>>(x, W1, h1, as1, ad1, asrc, adst,
                                                    N_NODES, 128, 256);
    }

    // ---- join, then aggregate layer 1 ----
    cudaStreamWaitEvent(0, ev_join, 0);
    agg1<<<nodeWarpBlocks, 256>>>(rowptr, col, h1, asrc, adst, b1, hid);

    // ---- layer 2 ----
    zero_dots<<<nodeBlocks, 256>>>(asrc, adst);
    {
        dim3 grid(1, (N_NODES + 127) / 128);
        bf16_gemm_dots<128, 64, 32><<<grid, 256>>>(hid, W2, h2, as2, ad2, asrc, adst,
                                                   N_NODES, 64, 128);
    }
    agg2<<<nodeWarpBlocks, 256>>>(rowptr, col, h2, asrc, adst, b2, out);
}

// round 12
// speedup vs baseline: 1.8002x; 1.4721x over previous
#include <cuda_runtime.h>
#include <cuda_bf16.h>
#include <math.h>
#include <stdint.h>

#define N_NODES 50000
#define NEG_SLOPE 0.2f
#define MAX_E 1200000
#define SCAN_CHUNK 512
#define NUM_SCAN_BLOCKS ((N_NODES + SCAN_CHUNK - 1) / SCAN_CHUNK)

// ---------------- device scratch (no allocs allowed) ----------------
__device__ float g_h1 [(size_t)N_NODES * 128];
__device__ float g_hid[(size_t)N_NODES * 128];
__device__ float g_h2 [(size_t)N_NODES * 64];
__device__ float g_asrc[N_NODES];
__device__ float g_adst[N_NODES];
__device__ float g_asrc2[N_NODES];
__device__ float g_adst2[N_NODES];
__device__ int   g_cnt[N_NODES];
__device__ int   g_rowptr[N_NODES + 1];
__device__ int   g_cur[N_NODES];
__device__ int   g_col[MAX_E];
__device__ int   g_bsum[NUM_SCAN_BLOCKS + 1];
__device__ int   g_idx64;

__device__ __forceinline__ float leaky_exp(float e) {
    e = (e > 0.f) ? e : NEG_SLOPE * e;
    return __expf(e);
}

// ---------------- parallel dtype detection (int32 vs int64) ----------------
// int64 little-endian values < 2^31 -> every odd 32-bit word is 0.
__global__ void detect_idx_dtype_par(const int* __restrict__ ei32) {
    __shared__ int nz;
    if (threadIdx.x == 0) nz = 0;
    __syncthreads();
    if (ei32[threadIdx.x * 2 + 1] != 0) atomicAdd(&nz, 1);
    __syncthreads();
    if (threadIdx.x == 0) g_idx64 = (nz == 0);
}

// ---------------- zero attention-dot accumulators ----------------
__global__ void zero_dots(float* __restrict__ asrc, float* __restrict__ adst) {
    int i = blockIdx.x * blockDim.x + threadIdx.x;
    if (i < N_NODES) { asrc[i] = 0.f; adst[i] = 0.f; }
}

// ---------------- CSR build ----------------
__global__ void zero_counts(int* __restrict__ cnt) {
    int i = blockIdx.x * blockDim.x + threadIdx.x;
    if (i < N_NODES) cnt[i] = 0;
}

__global__ void count_edges(const void* __restrict__ ei, int E, int* __restrict__ cnt) {
    int i = blockIdx.x * blockDim.x + threadIdx.x;
    if (i >= E) return;
    int d;
    if (g_idx64) d = (int)((const long long*)ei)[(size_t)E + i];
    else         d = ((const int*)ei)[E + i];
    atomicAdd(cnt + d, 1);
}

__global__ void scan_block(const int* __restrict__ cnt, int* __restrict__ rowptr,
                           int* __restrict__ bsum) {
    __shared__ int sm[SCAN_CHUNK];
    int b = blockIdx.x, t = threadIdx.x;
    int i = b * SCAN_CHUNK + t;
    int v = (i < N_NODES) ? cnt[i] : 0;
    sm[t] = v;
    __syncthreads();
#pragma unroll
    for (int o = 1; o < SCAN_CHUNK; o <<= 1) {
        int x = (t >= o) ? sm[t - o] : 0;
        __syncthreads();
        sm[t] += x;
        __syncthreads();
    }
    if (i < N_NODES) rowptr[i] = sm[t] - v;  // exclusive
    if (t == SCAN_CHUNK - 1) bsum[b] = sm[t];
}

__global__ void scan_bsums(int* __restrict__ bsum) {
    __shared__ int sm[NUM_SCAN_BLOCKS];
    int t = threadIdx.x;
    if (t < NUM_SCAN_BLOCKS) sm[t] = bsum[t];
    __syncthreads();
    if (t == 0) {
        int acc = 0;
        for (int i = 0; i < NUM_SCAN_BLOCKS; i++) { int v = sm[i]; sm[i] = acc; acc += v; }
    }
    __syncthreads();
    if (t < NUM_SCAN_BLOCKS) bsum[t] = sm[t];
}

__global__ void add_offsets(int* __restrict__ rowptr, const int* __restrict__ bsum,
                            int* __restrict__ cur, int E) {
    int i = blockIdx.x * blockDim.x + threadIdx.x;
    if (i < N_NODES) {
        int r = rowptr[i] + bsum[i / SCAN_CHUNK];
        rowptr[i] = r;
        cur[i] = r;
    }
    if (i == 0) rowptr[N_NODES] = E;
}

__global__ void scatter_edges(const void* __restrict__ ei, int E,
                              int* __restrict__ cur, int* __restrict__ col) {
    int i = blockIdx.x * blockDim.x + threadIdx.x;
    if (i >= E) return;
    int s, d;
    if (g_idx64) {
        const long long* p = (const long long*)ei;
        s = (int)p[i];
        d = (int)p[(size_t)E + i];
    } else {
        const int* p = (const int*)ei;
        s = p[i];
        d = p[E + i];
    }
    int pos = atomicAdd(cur + d, 1);
    col[pos] = s;
}

// ---------------- bf16 3-term split tensor-core GEMM + fused dots, cp.async pipelined ----------------
__device__ __forceinline__ void split_pack(float v0, float v1, uint32_t& big, uint32_t& sml) {
    __nv_bfloat162 b2 = __floats2bfloat162_rn(v0, v1);
    float2 f2 = __bfloat1622float2(b2);
    __nv_bfloat162 s2 = __floats2bfloat162_rn(v0 - f2.x, v1 - f2.y);
    big = *reinterpret_cast<uint32_t*>(&b2);
    sml = *reinterpret_cast<uint32_t*>(&s2);
}

__device__ __forceinline__ void mma_bf16(float* c, const uint32_t* a, const uint32_t* b) {
    asm volatile(
        "mma.sync.aligned.m16n8k16.row.col.f32.bf16.bf16.f32 "
        "{%0,%1,%2,%3}, {%4,%5,%6,%7}, {%8,%9}, {%0,%1,%2,%3};"
        : "+f"(c[0]), "+f"(c[1]), "+f"(c[2]), "+f"(c[3])
        : "r"(a[0]), "r"(a[1]), "r"(a[2]), "r"(a[3]), "r"(b[0]), "r"(b[1]));
}

__device__ __forceinline__ void cp_async16(uint32_t saddr, const void* gmem, int srcsize) {
    asm volatile("cp.async.ca.shared.global [%0], [%1], 16, %2;"
                 :: "r"(saddr), "l"(gmem), "r"(srcsize));
}
__device__ __forceinline__ void cp_commit() {
    asm volatile("cp.async.commit_group;");
}
__device__ __forceinline__ void cp_wait_all() {
    asm volatile("cp.async.wait_group 0;");
}

// A [M,K] row-major, B [K,N] row-major, C [M,N]. K%BK==0, BN==N (single block col).
// 8 warps, warp grid 4x2, 2-stage cp.async double buffer in dynamic smem.
// Epilogue also accumulates asrc/adst = C·att_s / C·att_d per row (atomic).
template <int BM, int BN, int BK>
__global__ void bf16_gemm_dots(const float* __restrict__ A, const float* __restrict__ B,
                               float* __restrict__ C,
                               const float* __restrict__ att_s, const float* __restrict__ att_d,
                               float* __restrict__ asrc, float* __restrict__ adst,
                               int M, int N, int K) {
    constexpr int WR = 4, WC = 2;
    constexpr int nThreads = WR * WC * 32;
    constexpr int WM = BM / WR;          // 32
    constexpr int WN = BN / WC;          // 64 or 32
    constexpr int MT = WM / 16;          // 2
    constexpr int NT = WN / 8;           // 8 or 4
    constexpr int KS = BK / 16;          // 2
    constexpr int APAD = 4, BPAD = 8;
    constexpr int ASTRIDE = BK + APAD;
    constexpr int BSTRIDE = BN + BPAD;
    constexpr int A_BUF = BM * ASTRIDE;
    constexpr int B_BUF = BK * BSTRIDE;

    extern __shared__ float dynsmem[];
    float* Abase = dynsmem;              // [2][BM][ASTRIDE]
    float* Bbase = dynsmem + 2 * A_BUF;  // [2][BK][BSTRIDE]

    int tid = threadIdx.x;
    int wid = tid >> 5;
    int lane = tid & 31;
    int wr = wid / WC, wc = wid % WC;
    int row0 = blockIdx.y * BM;
    int grp = lane >> 2;
    int qd  = lane & 3;

    const int NIT = K / BK;

    auto prefetch = [&](int k0, int buf) {
        float* As = Abase + buf * A_BUF;
        float* Bs = Bbase + buf * B_BUF;
#pragma unroll
        for (int i = tid; i < BM * BK / 4; i += nThreads) {
            int r = i / (BK / 4);
            int c4 = i % (BK / 4);
            int gr = row0 + r;
            const float* src = A + ((gr < M) ? ((size_t)gr * K + k0 + c4 * 4) : 0);
            uint32_t sa = (uint32_t)__cvta_generic_to_shared(&As[r * ASTRIDE + c4 * 4]);
            cp_async16(sa, src, (gr < M) ? 16 : 0);
        }
#pragma unroll
        for (int i = tid; i < BK * BN / 4; i += nThreads) {
            int r = i / (BN / 4);
            int c4 = i % (BN / 4);
            const float* src = B + (size_t)(k0 + r) * N + c4 * 4;
            uint32_t sb = (uint32_t)__cvta_generic_to_shared(&Bs[r * BSTRIDE + c4 * 4]);
            cp_async16(sb, src, 16);
        }
        cp_commit();
    };

    float acc[MT][NT][4];
#pragma unroll
    for (int i = 0; i < MT; i++)
#pragma unroll
        for (int j = 0; j < NT; j++)
#pragma unroll
            for (int q = 0; q < 4; q++) acc[i][j][q] = 0.f;

    prefetch(0, 0);
    int buf = 0;

    for (int it = 0; it < NIT; it++) {
        cp_wait_all();
        __syncthreads();                 // data ready AND all warps done with prior compute
        if (it + 1 < NIT) prefetch((it + 1) * BK, buf ^ 1);

        float* As = Abase + buf * A_BUF;
        float* Bs = Bbase + buf * B_BUF;

#pragma unroll
        for (int ks = 0; ks < KS; ks++) {
            int kc = ks * 16 + qd * 2;
            uint32_t abig[MT][4], asml[MT][4];
#pragma unroll
            for (int mt = 0; mt < MT; mt++) {
                int rb = wr * WM + mt * 16 + grp;
                split_pack(As[rb * ASTRIDE + kc],           As[rb * ASTRIDE + kc + 1],
                           abig[mt][0], asml[mt][0]);
                split_pack(As[(rb + 8) * ASTRIDE + kc],     As[(rb + 8) * ASTRIDE + kc + 1],
                           abig[mt][1], asml[mt][1]);
                split_pack(As[rb * ASTRIDE + kc + 8],       As[rb * ASTRIDE + kc + 9],
                           abig[mt][2], asml[mt][2]);
                split_pack(As[(rb + 8) * ASTRIDE + kc + 8], As[(rb + 8) * ASTRIDE + kc + 9],
                           abig[mt][3], asml[mt][3]);
            }
#pragma unroll
            for (int nt = 0; nt < NT; nt++) {
                int n = wc * WN + nt * 8 + grp;
                int kb = ks * 16 + qd * 2;
                uint32_t bbig[2], bsml[2];
                split_pack(Bs[kb * BSTRIDE + n],       Bs[(kb + 1) * BSTRIDE + n],
                           bbig[0], bsml[0]);
                split_pack(Bs[(kb + 8) * BSTRIDE + n], Bs[(kb + 9) * BSTRIDE + n],
                           bbig[1], bsml[1]);
#pragma unroll
                for (int mt = 0; mt < MT; mt++) {
                    mma_bf16(acc[mt][nt], abig[mt], bbig);
                    mma_bf16(acc[mt][nt], abig[mt], bsml);
                    mma_bf16(acc[mt][nt], asml[mt], bbig);
                }
            }
        }
        buf ^= 1;
    }

    // ---- epilogue: store C + fused per-row attention dots ----
    float ss[MT][2], sd[MT][2];
#pragma unroll
    for (int mt = 0; mt < MT; mt++) { ss[mt][0] = ss[mt][1] = sd[mt][0] = sd[mt][1] = 0.f; }

#pragma unroll
    for (int mt = 0; mt < MT; mt++) {
#pragma unroll
        for (int nt = 0; nt < NT; nt++) {
            int row = row0 + wr * WM + mt * 16 + grp;
            int col = wc * WN + nt * 8 + qd * 2;
            if (row < M)
                *(float2*)(C + (size_t)row * N + col) =
                    make_float2(acc[mt][nt][0], acc[mt][nt][1]);
            if (row + 8 < M)
                *(float2*)(C + (size_t)(row + 8) * N + col) =
                    make_float2(acc[mt][nt][2], acc[mt][nt][3]);

            float a0 = att_s[col], a1 = att_s[col + 1];
            float d0 = att_d[col], d1 = att_d[col + 1];
            ss[mt][0] += acc[mt][nt][0] * a0 + acc[mt][nt][1] * a1;
            ss[mt][1] += acc[mt][nt][2] * a0 + acc[mt][nt][3] * a1;
            sd[mt][0] += acc[mt][nt][0] * d0 + acc[mt][nt][1] * d1;
            sd[mt][1] += acc[mt][nt][2] * d0 + acc[mt][nt][3] * d1;
        }
    }
#pragma unroll
    for (int mt = 0; mt < MT; mt++) {
#pragma unroll
        for (int h = 0; h < 2; h++) {
            float vs = ss[mt][h], vd = sd[mt][h];
            vs += __shfl_xor_sync(0xffffffffu, vs, 1);
            vs += __shfl_xor_sync(0xffffffffu, vs, 2);
            vd += __shfl_xor_sync(0xffffffffu, vd, 1);
            vd += __shfl_xor_sync(0xffffffffu, vd, 2);
            if (qd == 0) {
                int row = row0 + wr * WM + mt * 16 + grp + h * 8;
                if (row < M) {
                    atomicAdd(asrc + row, vs);
                    atomicAdd(adst + row, vd);
                }
            }
        }
    }
}

// ---------------- fused gather-aggregate layer 1 (C=128): softmax + bias + ReLU ----------------
__global__ void agg1(const int* __restrict__ rowptr, const int* __restrict__ col,
                     const float* __restrict__ h, const float* __restrict__ asrc,
                     const float* __restrict__ adst, const float* __restrict__ bias,
                     float* __restrict__ out) {
    int warp = (blockIdx.x * blockDim.x + threadIdx.x) >> 5;
    int lane = threadIdx.x & 31;
    if (warp >= N_NODES) return;
    int d = warp;
    float ad = adst[d];

    float ee = leaky_exp(asrc[d] + ad);
    float4 hv = ((const float4*)(h + (size_t)d * 128))[lane];
    float ax = hv.x * ee, ay = hv.y * ee, az = hv.z * ee, aw = hv.w * ee;
    float denom = ee;

    int beg = rowptr[d], end = rowptr[d + 1];
    for (int j0 = beg; j0 < end; j0 += 32) {
        int idx = j0 + lane;
        int sj = 0;
        float aj = 0.f;
        if (idx < end) { sj = col[idx]; aj = asrc[sj]; }
        int cnt = min(32, end - j0);
#pragma unroll 4
        for (int j = 0; j < cnt; j++) {
            int s = __shfl_sync(0xffffffffu, sj, j);
            float a = __shfl_sync(0xffffffffu, aj, j);
            float w = leaky_exp(a + ad);
            float4 x = ((const float4*)(h + (size_t)s * 128))[lane];
            ax += w * x.x; ay += w * x.y; az += w * x.z; aw += w * x.w;
            denom += w;
        }
    }
    float inv = 1.f / denom;
    float4 b4 = ((const float4*)bias)[lane];
    float4 o;
    o.x = fmaxf(ax * inv + b4.x, 0.f);
    o.y = fmaxf(ay * inv + b4.y, 0.f);
    o.z = fmaxf(az * inv + b4.z, 0.f);
    o.w = fmaxf(aw * inv + b4.w, 0.f);
    ((float4*)(out + (size_t)d * 128))[lane] = o;
}

// ---------------- fused gather-aggregate layer 2 (C=64): softmax + bias + log_softmax ----------------
__global__ void agg2(const int* __restrict__ rowptr, const int* __restrict__ col,
                     const float* __restrict__ h, const float* __restrict__ asrc,
                     const float* __restrict__ adst, const float* __restrict__ bias,
                     float* __restrict__ out) {
    int warp = (blockIdx.x * blockDim.x + threadIdx.x) >> 5;
    int lane = threadIdx.x & 31;
    if (warp >= N_NODES) return;
    int d = warp;
    float ad = adst[d];

    float ee = leaky_exp(asrc[d] + ad);
    float2 hv = ((const float2*)(h + (size_t)d * 64))[lane];
    float ax = hv.x * ee, ay = hv.y * ee;
    float denom = ee;

    int beg = rowptr[d], end = rowptr[d + 1];
    for (int j0 = beg; j0 < end; j0 += 32) {
        int idx = j0 + lane;
        int sj = 0;
        float aj = 0.f;
        if (idx < end) { sj = col[idx]; aj = asrc[sj]; }
        int cnt = min(32, end - j0);
#pragma unroll 4
        for (int j = 0; j < cnt; j++) {
            int s = __shfl_sync(0xffffffffu, sj, j);
            float a = __shfl_sync(0xffffffffu, aj, j);
            float w = leaky_exp(a + ad);
            float2 x = ((const float2*)(h + (size_t)s * 64))[lane];
            ax += w * x.x; ay += w * x.y;
            denom += w;
        }
    }
    float inv = 1.f / denom;
    float2 b2 = ((const float2*)bias)[lane];
    float v0 = ax * inv + b2.x;
    float v1 = ay * inv + b2.y;
    float m = fmaxf(v0, v1);
#pragma unroll
    for (int o = 16; o > 0; o >>= 1) m = fmaxf(m, __shfl_xor_sync(0xffffffffu, m, o));
    float sm = __expf(v0 - m) + __expf(v1 - m);
#pragma unroll
    for (int o = 16; o > 0; o >>= 1) sm += __shfl_xor_sync(0xffffffffu, sm, o);
    float lse = m + logf(sm);
    float2 o2;
    o2.x = v0 - lse;
    o2.y = v1 - lse;
    ((float2*)(out + (size_t)d * 64))[lane] = o2;
}

// ---------------- host orchestration ----------------
extern "C" void kernel_launch(void* const* d_in, const int* in_sizes, int n_in,
                              void* d_out, int out_size) {
    const float* x   = (const float*)d_in[0];
    const void*  ei  = d_in[1];
    const float* W1  = (const float*)d_in[2];
    const float* as1 = (const float*)d_in[3];
    const float* ad1 = (const float*)d_in[4];
    const float* b1  = (const float*)d_in[5];
    const float* W2  = (const float*)d_in[6];
    const float* as2 = (const float*)d_in[7];
    const float* ad2 = (const float*)d_in[8];
    const float* b2  = (const float*)d_in[9];
    float* out = (float*)d_out;

    int E = in_sizes[1] / 2;

    float *h1, *hid, *h2, *asrc, *adst, *asrc2, *adst2;
    int *cnt, *rowptr, *cur, *col, *bsum;
    cudaGetSymbolAddress((void**)&h1,  g_h1);
    cudaGetSymbolAddress((void**)&hid, g_hid);
    cudaGetSymbolAddress((void**)&h2,  g_h2);
    cudaGetSymbolAddress((void**)&asrc, g_asrc);
    cudaGetSymbolAddress((void**)&adst, g_adst);
    cudaGetSymbolAddress((void**)&asrc2, g_asrc2);
    cudaGetSymbolAddress((void**)&adst2, g_adst2);
    cudaGetSymbolAddress((void**)&cnt, g_cnt);
    cudaGetSymbolAddress((void**)&rowptr, g_rowptr);
    cudaGetSymbolAddress((void**)&cur, g_cur);
    cudaGetSymbolAddress((void**)&col, g_col);
    cudaGetSymbolAddress((void**)&bsum, g_bsum);

    // dynamic smem sizes for the pipelined GEMMs
    const int SMEM1 = (2 * 128 * (32 + 4) + 2 * 32 * (128 + 8)) * 4;  // 71680
    const int SMEM2 = (2 * 128 * (32 + 4) + 2 * 32 * (64 + 8)) * 4;   // 55296

    // one-time handle creation (host-side only; no device memory involved)
    static cudaStream_t s_side = nullptr;
    static cudaEvent_t ev_fork = nullptr, ev_join = nullptr;
    if (!s_side) {
        cudaStreamCreateWithFlags(&s_side, cudaStreamNonBlocking);
        cudaEventCreateWithFlags(&ev_fork, cudaEventDisableTiming);
        cudaEventCreateWithFlags(&ev_join, cudaEventDisableTiming);
        cudaFuncSetAttribute(bf16_gemm_dots<128, 128, 32>,
                             cudaFuncAttributeMaxDynamicSharedMemorySize, SMEM1);
        cudaFuncSetAttribute(bf16_gemm_dots<128, 64, 32>,
                             cudaFuncAttributeMaxDynamicSharedMemorySize, SMEM2);
    }

    const int nodeBlocks = (N_NODES + 255) / 256;
    const int nodeWarpBlocks = (N_NODES * 32 + 255) / 256;
    const int edgeBlocks = (E + 255) / 256;

    // ---- prologue on main stream (cheap, parallel) ----
    detect_idx_dtype_par<<<1, 128>>>((const int*)ei);
    zero_dots<<<nodeBlocks, 256>>>(asrc, adst);

    // ---- fork: CSR build + layer-2 dot zeroing on side stream, concurrent with gemm1 ----
    cudaEventRecord(ev_fork, 0);
    cudaStreamWaitEvent(s_side, ev_fork, 0);

    zero_counts<<<nodeBlocks, 256, 0, s_side>>>(cnt);
    zero_dots<<<nodeBlocks, 256, 0, s_side>>>(asrc2, adst2);
    count_edges<<<edgeBlocks, 256, 0, s_side>>>(ei, E, cnt);
    scan_block<<<NUM_SCAN_BLOCKS, SCAN_CHUNK, 0, s_side>>>(cnt, rowptr, bsum);
    scan_bsums<<<1, 128, 0, s_side>>>(bsum);
    add_offsets<<<nodeBlocks, 256, 0, s_side>>>(rowptr, bsum, cur, E);
    scatter_edges<<<edgeBlocks, 256, 0, s_side>>>(ei, E, cur, col);
    cudaEventRecord(ev_join, s_side);

    // ---- main stream: layer-1 GEMM with fused dots ----
    {
        dim3 grid(1, (N_NODES + 127) / 128);
        bf16_gemm_dots<128, 128, 32><<<grid, 256, SMEM1>>>(x, W1, h1, as1, ad1, asrc, adst,
                                                           N_NODES, 128, 256);
    }

    // ---- join, then aggregate layer 1 ----
    cudaStreamWaitEvent(0, ev_join, 0);
    agg1<<<nodeWarpBlocks, 256>>>(rowptr, col, h1, asrc, adst, b1, hid);

    // ---- layer 2 ----
    {
        dim3 grid(1, (N_NODES + 127) / 128);
        bf16_gemm_dots<128, 64, 32><<<grid, 256, SMEM2>>>(hid, W2, h2, as2, ad2, asrc2, adst2,
                                                          N_NODES, 64, 128);
    }
    agg2<<<nodeWarpBlocks, 256>>>(rowptr, col, h2, asrc2, adst2, b2, out);
}

// round 13
// speedup vs baseline: 1.8299x; 1.0165x over previous
#include <cuda_runtime.h>
#include <cuda_bf16.h>
#include <cuda_fp16.h>
#include <math.h>
#include <stdint.h>

#define N_NODES 50000
#define NEG_SLOPE 0.2f
#define MAX_E 1200000
#define SCAN_CHUNK 512
#define NUM_SCAN_BLOCKS ((N_NODES + SCAN_CHUNK - 1) / SCAN_CHUNK)

// ---------------- device scratch (no allocs allowed) ----------------
__device__ __half g_h1 [(size_t)N_NODES * 128];   // fp16 gather operand, layer 1
__device__ float  g_hid[(size_t)N_NODES * 128];   // fp32 layer-2 GEMM input
__device__ __half g_h2 [(size_t)N_NODES * 64];    // fp16 gather operand, layer 2
__device__ float  g_asrc[N_NODES];
__device__ float  g_adst[N_NODES];
__device__ float  g_asrc2[N_NODES];
__device__ float  g_adst2[N_NODES];
__device__ int    g_cnt[N_NODES];
__device__ int    g_rowptr[N_NODES + 1];
__device__ int    g_cur[N_NODES];
__device__ int    g_col[MAX_E];
__device__ int    g_bsum[NUM_SCAN_BLOCKS + 1];
__device__ int    g_idx64;

__device__ __forceinline__ float leaky_exp(float e) {
    e = (e > 0.f) ? e : NEG_SLOPE * e;
    return __expf(e);
}

// ---------------- parallel dtype detection (int32 vs int64) ----------------
__global__ void detect_idx_dtype_par(const int* __restrict__ ei32) {
    __shared__ int nz;
    if (threadIdx.x == 0) nz = 0;
    __syncthreads();
    if (ei32[threadIdx.x * 2 + 1] != 0) atomicAdd(&nz, 1);
    __syncthreads();
    if (threadIdx.x == 0) g_idx64 = (nz == 0);
}

// ---------------- CSR build ----------------
__global__ void zero_counts(int* __restrict__ cnt) {
    int i = blockIdx.x * blockDim.x + threadIdx.x;
    if (i < N_NODES) cnt[i] = 0;
}

__global__ void count_edges(const void* __restrict__ ei, int E, int* __restrict__ cnt) {
    int i = blockIdx.x * blockDim.x + threadIdx.x;
    if (i >= E) return;
    int d;
    if (g_idx64) d = (int)((const long long*)ei)[(size_t)E + i];
    else         d = ((const int*)ei)[E + i];
    atomicAdd(cnt + d, 1);
}

__global__ void scan_block(const int* __restrict__ cnt, int* __restrict__ rowptr,
                           int* __restrict__ bsum) {
    __shared__ int sm[SCAN_CHUNK];
    int b = blockIdx.x, t = threadIdx.x;
    int i = b * SCAN_CHUNK + t;
    int v = (i < N_NODES) ? cnt[i] : 0;
    sm[t] = v;
    __syncthreads();
#pragma unroll
    for (int o = 1; o < SCAN_CHUNK; o <<= 1) {
        int x = (t >= o) ? sm[t - o] : 0;
        __syncthreads();
        sm[t] += x;
        __syncthreads();
    }
    if (i < N_NODES) rowptr[i] = sm[t] - v;  // exclusive
    if (t == SCAN_CHUNK - 1) bsum[b] = sm[t];
}

__global__ void scan_bsums(int* __restrict__ bsum) {
    __shared__ int sm[NUM_SCAN_BLOCKS];
    int t = threadIdx.x;
    if (t < NUM_SCAN_BLOCKS) sm[t] = bsum[t];
    __syncthreads();
    if (t == 0) {
        int acc = 0;
        for (int i = 0; i < NUM_SCAN_BLOCKS; i++) { int v = sm[i]; sm[i] = acc; acc += v; }
    }
    __syncthreads();
    if (t < NUM_SCAN_BLOCKS) bsum[t] = sm[t];
}

__global__ void add_offsets(int* __restrict__ rowptr, const int* __restrict__ bsum,
                            int* __restrict__ cur, int E) {
    int i = blockIdx.x * blockDim.x + threadIdx.x;
    if (i < N_NODES) {
        int r = rowptr[i] + bsum[i / SCAN_CHUNK];
        rowptr[i] = r;
        cur[i] = r;
    }
    if (i == 0) rowptr[N_NODES] = E;
}

__global__ void scatter_edges(const void* __restrict__ ei, int E,
                              int* __restrict__ cur, int* __restrict__ col) {
    int i = blockIdx.x * blockDim.x + threadIdx.x;
    if (i >= E) return;
    int s, d;
    if (g_idx64) {
        const long long* p = (const long long*)ei;
        s = (int)p[i];
        d = (int)p[(size_t)E + i];
    } else {
        const int* p = (const int*)ei;
        s = p[i];
        d = p[E + i];
    }
    int pos = atomicAdd(cur + d, 1);
    col[pos] = s;
}

// ---------------- bf16 3-term split tensor-core GEMM + fused dots, cp.async pipelined ----------------
__device__ __forceinline__ void split_pack(float v0, float v1, uint32_t& big, uint32_t& sml) {
    __nv_bfloat162 b2 = __floats2bfloat162_rn(v0, v1);
    float2 f2 = __bfloat1622float2(b2);
    __nv_bfloat162 s2 = __floats2bfloat162_rn(v0 - f2.x, v1 - f2.y);
    big = *reinterpret_cast<uint32_t*>(&b2);
    sml = *reinterpret_cast<uint32_t*>(&s2);
}

__device__ __forceinline__ void mma_bf16(float* c, const uint32_t* a, const uint32_t* b) {
    asm volatile(
        "mma.sync.aligned.m16n8k16.row.col.f32.bf16.bf16.f32 "
        "{%0,%1,%2,%3}, {%4,%5,%6,%7}, {%8,%9}, {%0,%1,%2,%3};"
        : "+f"(c[0]), "+f"(c[1]), "+f"(c[2]), "+f"(c[3])
        : "r"(a[0]), "r"(a[1]), "r"(a[2]), "r"(a[3]), "r"(b[0]), "r"(b[1]));
}

__device__ __forceinline__ void cp_async16(uint32_t saddr, const void* gmem, int srcsize) {
    asm volatile("cp.async.ca.shared.global [%0], [%1], 16, %2;"
                 :: "r"(saddr), "l"(gmem), "r"(srcsize));
}
__device__ __forceinline__ void cp_commit() {
    asm volatile("cp.async.commit_group;");
}
__device__ __forceinline__ void cp_wait_all() {
    asm volatile("cp.async.wait_group 0;");
}

// A [M,K] row-major fp32, B [K,N] row-major fp32, C [M,N] fp16. BN==N (single block col).
// 8 warps, warp grid 4x2, 2-stage cp.async double buffer.
// Epilogue: fp16 C store + per-row dots (smem block reduction, plain global store).
template <int BM, int BN, int BK>
__global__ void bf16_gemm_dots(const float* __restrict__ A, const float* __restrict__ B,
                               __half* __restrict__ C,
                               const float* __restrict__ att_s, const float* __restrict__ att_d,
                               float* __restrict__ asrc, float* __restrict__ adst,
                               int M, int N, int K) {
    constexpr int WR = 4, WC = 2;
    constexpr int nThreads = WR * WC * 32;
    constexpr int WM = BM / WR;          // 32
    constexpr int WN = BN / WC;          // 64 or 32
    constexpr int MT = WM / 16;          // 2
    constexpr int NT = WN / 8;           // 8 or 4
    constexpr int KS = BK / 16;          // 2
    constexpr int APAD = 4, BPAD = 8;
    constexpr int ASTRIDE = BK + APAD;
    constexpr int BSTRIDE = BN + BPAD;
    constexpr int A_BUF = BM * ASTRIDE;
    constexpr int B_BUF = BK * BSTRIDE;

    extern __shared__ float dynsmem[];
    float* Abase = dynsmem;              // [2][BM][ASTRIDE]
    float* Bbase = dynsmem + 2 * A_BUF;  // [2][BK][BSTRIDE]

    int tid = threadIdx.x;
    int wid = tid >> 5;
    int lane = tid & 31;
    int wr = wid / WC, wc = wid % WC;
    int row0 = blockIdx.y * BM;
    int grp = lane >> 2;
    int qd  = lane & 3;

    const int NIT = K / BK;

    auto prefetch = [&](int k0, int buf) {
        float* As = Abase + buf * A_BUF;
        float* Bs = Bbase + buf * B_BUF;
#pragma unroll
        for (int i = tid; i < BM * BK / 4; i += nThreads) {
            int r = i / (BK / 4);
            int c4 = i % (BK / 4);
            int gr = row0 + r;
            const float* src = A + ((gr < M) ? ((size_t)gr * K + k0 + c4 * 4) : 0);
            uint32_t sa = (uint32_t)__cvta_generic_to_shared(&As[r * ASTRIDE + c4 * 4]);
            cp_async16(sa, src, (gr < M) ? 16 : 0);
        }
#pragma unroll
        for (int i = tid; i < BK * BN / 4; i += nThreads) {
            int r = i / (BN / 4);
            int c4 = i % (BN / 4);
            const float* src = B + (size_t)(k0 + r) * N + c4 * 4;
            uint32_t sb = (uint32_t)__cvta_generic_to_shared(&Bs[r * BSTRIDE + c4 * 4]);
            cp_async16(sb, src, 16);
        }
        cp_commit();
    };

    float acc[MT][NT][4];
#pragma unroll
    for (int i = 0; i < MT; i++)
#pragma unroll
        for (int j = 0; j < NT; j++)
#pragma unroll
            for (int q = 0; q < 4; q++) acc[i][j][q] = 0.f;

    prefetch(0, 0);
    int buf = 0;

    for (int it = 0; it < NIT; it++) {
        cp_wait_all();
        __syncthreads();
        if (it + 1 < NIT) prefetch((it + 1) * BK, buf ^ 1);

        float* As = Abase + buf * A_BUF;
        float* Bs = Bbase + buf * B_BUF;

#pragma unroll
        for (int ks = 0; ks < KS; ks++) {
            int kc = ks * 16 + qd * 2;
            uint32_t abig[MT][4], asml[MT][4];
#pragma unroll
            for (int mt = 0; mt < MT; mt++) {
                int rb = wr * WM + mt * 16 + grp;
                split_pack(As[rb * ASTRIDE + kc],           As[rb * ASTRIDE + kc + 1],
                           abig[mt][0], asml[mt][0]);
                split_pack(As[(rb + 8) * ASTRIDE + kc],     As[(rb + 8) * ASTRIDE + kc + 1],
                           abig[mt][1], asml[mt][1]);
                split_pack(As[rb * ASTRIDE + kc + 8],       As[rb * ASTRIDE + kc + 9],
                           abig[mt][2], asml[mt][2]);
                split_pack(As[(rb + 8) * ASTRIDE + kc + 8], As[(rb + 8) * ASTRIDE + kc + 9],
                           abig[mt][3], asml[mt][3]);
            }
#pragma unroll
            for (int nt = 0; nt < NT; nt++) {
                int n = wc * WN + nt * 8 + grp;
                int kb = ks * 16 + qd * 2;
                uint32_t bbig[2], bsml[2];
                split_pack(Bs[kb * BSTRIDE + n],       Bs[(kb + 1) * BSTRIDE + n],
                           bbig[0], bsml[0]);
                split_pack(Bs[(kb + 8) * BSTRIDE + n], Bs[(kb + 9) * BSTRIDE + n],
                           bbig[1], bsml[1]);
#pragma unroll
                for (int mt = 0; mt < MT; mt++) {
                    mma_bf16(acc[mt][nt], abig[mt], bbig);
                    mma_bf16(acc[mt][nt], abig[mt], bsml);
                    mma_bf16(acc[mt][nt], asml[mt], bbig);
                }
            }
        }
        buf ^= 1;
    }

    // ---- epilogue: fp16 C store + dots via smem block reduction ----
    __syncthreads();                 // all compute done; smem reusable
    float* ssm = dynsmem;            // [BM]
    float* sdm = dynsmem + BM;       // [BM]
    if (tid < BM) { ssm[tid] = 0.f; sdm[tid] = 0.f; }
    __syncthreads();

    float ss[MT][2], sd[MT][2];
#pragma unroll
    for (int mt = 0; mt < MT; mt++) { ss[mt][0] = ss[mt][1] = sd[mt][0] = sd[mt][1] = 0.f; }

#pragma unroll
    for (int mt = 0; mt < MT; mt++) {
#pragma unroll
        for (int nt = 0; nt < NT; nt++) {
            int row = row0 + wr * WM + mt * 16 + grp;
            int col = wc * WN + nt * 8 + qd * 2;
            if (row < M)
                *(__half2*)(C + (size_t)row * N + col) =
                    __floats2half2_rn(acc[mt][nt][0], acc[mt][nt][1]);
            if (row + 8 < M)
                *(__half2*)(C + (size_t)(row + 8) * N + col) =
                    __floats2half2_rn(acc[mt][nt][2], acc[mt][nt][3]);

            float a0 = att_s[col], a1 = att_s[col + 1];
            float d0 = att_d[col], d1 = att_d[col + 1];
            ss[mt][0] += acc[mt][nt][0] * a0 + acc[mt][nt][1] * a1;
            ss[mt][1] += acc[mt][nt][2] * a0 + acc[mt][nt][3] * a1;
            sd[mt][0] += acc[mt][nt][0] * d0 + acc[mt][nt][1] * d1;
            sd[mt][1] += acc[mt][nt][2] * d0 + acc[mt][nt][3] * d1;
        }
    }
#pragma unroll
    for (int mt = 0; mt < MT; mt++) {
#pragma unroll
        for (int h = 0; h < 2; h++) {
            float vs = ss[mt][h], vd = sd[mt][h];
            vs += __shfl_xor_sync(0xffffffffu, vs, 1);
            vs += __shfl_xor_sync(0xffffffffu, vs, 2);
            vd += __shfl_xor_sync(0xffffffffu, vd, 1);
            vd += __shfl_xor_sync(0xffffffffu, vd, 2);
            if (qd == 0) {
                int rl = wr * WM + mt * 16 + grp + h * 8;
                atomicAdd(&ssm[rl], vs);
                atomicAdd(&sdm[rl], vd);
            }
        }
    }
    __syncthreads();
    if (tid < BM) {
        int row = row0 + tid;
        if (row < M) { asrc[row] = ssm[tid]; adst[row] = sdm[tid]; }
    }
}

// ---------------- fused gather-aggregate layer 1 (C=128, fp16 h): softmax + bias + ReLU ----------------
__global__ void agg1(const int* __restrict__ rowptr, const int* __restrict__ col,
                     const __half* __restrict__ h, const float* __restrict__ asrc,
                     const float* __restrict__ adst, const float* __restrict__ bias,
                     float* __restrict__ out) {
    int warp = (blockIdx.x * blockDim.x + threadIdx.x) >> 5;
    int lane = threadIdx.x & 31;
    if (warp >= N_NODES) return;
    int d = warp;
    float ad = adst[d];

    float ee = leaky_exp(asrc[d] + ad);
    uint2 u = ((const uint2*)(h + (size_t)d * 128))[lane];
    float2 p0 = __half22float2(*(__half2*)&u.x);
    float2 p1 = __half22float2(*(__half2*)&u.y);
    float ax = p0.x * ee, ay = p0.y * ee, az = p1.x * ee, aw = p1.y * ee;
    float denom = ee;

    int beg = rowptr[d], end = rowptr[d + 1];
    for (int j0 = beg; j0 < end; j0 += 32) {
        int idx = j0 + lane;
        int sj = 0;
        float aj = 0.f;
        if (idx < end) { sj = col[idx]; aj = asrc[sj]; }
        int cnt = min(32, end - j0);
#pragma unroll 4
        for (int j = 0; j < cnt; j++) {
            int s = __shfl_sync(0xffffffffu, sj, j);
            float a = __shfl_sync(0xffffffffu, aj, j);
            float w = leaky_exp(a + ad);
            uint2 ux = ((const uint2*)(h + (size_t)s * 128))[lane];
            float2 x0 = __half22float2(*(__half2*)&ux.x);
            float2 x1 = __half22float2(*(__half2*)&ux.y);
            ax += w * x0.x; ay += w * x0.y; az += w * x1.x; aw += w * x1.y;
            denom += w;
        }
    }
    float inv = 1.f / denom;
    float4 b4 = ((const float4*)bias)[lane];
    float4 o;
    o.x = fmaxf(ax * inv + b4.x, 0.f);
    o.y = fmaxf(ay * inv + b4.y, 0.f);
    o.z = fmaxf(az * inv + b4.z, 0.f);
    o.w = fmaxf(aw * inv + b4.w, 0.f);
    ((float4*)(out + (size_t)d * 128))[lane] = o;
}

// ---------------- fused gather-aggregate layer 2 (C=64, fp16 h): softmax + bias + log_softmax ----------------
__global__ void agg2(const int* __restrict__ rowptr, const int* __restrict__ col,
                     const __half* __restrict__ h, const float* __restrict__ asrc,
                     const float* __restrict__ adst, const float* __restrict__ bias,
                     float* __restrict__ out) {
    int warp = (blockIdx.x * blockDim.x + threadIdx.x) >> 5;
    int lane = threadIdx.x & 31;
    if (warp >= N_NODES) return;
    int d = warp;
    float ad = adst[d];

    float ee = leaky_exp(asrc[d] + ad);
    float2 hv = __half22float2(((const __half2*)(h + (size_t)d * 64))[lane]);
    float ax = hv.x * ee, ay = hv.y * ee;
    float denom = ee;

    int beg = rowptr[d], end = rowptr[d + 1];
    for (int j0 = beg; j0 < end; j0 += 32) {
        int idx = j0 + lane;
        int sj = 0;
        float aj = 0.f;
        if (idx < end) { sj = col[idx]; aj = asrc[sj]; }
        int cnt = min(32, end - j0);
#pragma unroll 4
        for (int j = 0; j < cnt; j++) {
            int s = __shfl_sync(0xffffffffu, sj, j);
            float a = __shfl_sync(0xffffffffu, aj, j);
            float w = leaky_exp(a + ad);
            float2 x = __half22float2(((const __half2*)(h + (size_t)s * 64))[lane]);
            ax += w * x.x; ay += w * x.y;
            denom += w;
        }
    }
    float inv = 1.f / denom;
    float2 b2 = ((const float2*)bias)[lane];
    float v0 = ax * inv + b2.x;
    float v1 = ay * inv + b2.y;
    float m = fmaxf(v0, v1);
#pragma unroll
    for (int o = 16; o > 0; o >>= 1) m = fmaxf(m, __shfl_xor_sync(0xffffffffu, m, o));
    float sm = __expf(v0 - m) + __expf(v1 - m);
#pragma unroll
    for (int o = 16; o > 0; o >>= 1) sm += __shfl_xor_sync(0xffffffffu, sm, o);
    float lse = m + logf(sm);
    float2 o2;
    o2.x = v0 - lse;
    o2.y = v1 - lse;
    ((float2*)(out + (size_t)d * 64))[lane] = o2;
}

// ---------------- host orchestration ----------------
extern "C" void kernel_launch(void* const* d_in, const int* in_sizes, int n_in,
                              void* d_out, int out_size) {
    const float* x   = (const float*)d_in[0];
    const void*  ei  = d_in[1];
    const float* W1  = (const float*)d_in[2];
    const float* as1 = (const float*)d_in[3];
    const float* ad1 = (const float*)d_in[4];
    const float* b1  = (const float*)d_in[5];
    const float* W2  = (const float*)d_in[6];
    const float* as2 = (const float*)d_in[7];
    const float* ad2 = (const float*)d_in[8];
    const float* b2  = (const float*)d_in[9];
    float* out = (float*)d_out;

    int E = in_sizes[1] / 2;

    __half *h1, *h2;
    float *hid, *asrc, *adst, *asrc2, *adst2;
    int *cnt, *rowptr, *cur, *col, *bsum;
    cudaGetSymbolAddress((void**)&h1,  g_h1);
    cudaGetSymbolAddress((void**)&hid, g_hid);
    cudaGetSymbolAddress((void**)&h2,  g_h2);
    cudaGetSymbolAddress((void**)&asrc, g_asrc);
    cudaGetSymbolAddress((void**)&adst, g_adst);
    cudaGetSymbolAddress((void**)&asrc2, g_asrc2);
    cudaGetSymbolAddress((void**)&adst2, g_adst2);
    cudaGetSymbolAddress((void**)&cnt, g_cnt);
    cudaGetSymbolAddress((void**)&rowptr, g_rowptr);
    cudaGetSymbolAddress((void**)&cur, g_cur);
    cudaGetSymbolAddress((void**)&col, g_col);
    cudaGetSymbolAddress((void**)&bsum, g_bsum);

    const int SMEM1 = (2 * 128 * (32 + 4) + 2 * 32 * (128 + 8)) * 4;  // 71680
    const int SMEM2 = (2 * 128 * (32 + 4) + 2 * 32 * (64 + 8)) * 4;   // 55296

    static cudaStream_t s_side = nullptr;
    static cudaEvent_t ev_fork = nullptr, ev_join = nullptr;
    if (!s_side) {
        cudaStreamCreateWithFlags(&s_side, cudaStreamNonBlocking);
        cudaEventCreateWithFlags(&ev_fork, cudaEventDisableTiming);
        cudaEventCreateWithFlags(&ev_join, cudaEventDisableTiming);
        cudaFuncSetAttribute(bf16_gemm_dots<128, 128, 32>,
                             cudaFuncAttributeMaxDynamicSharedMemorySize, SMEM1);
        cudaFuncSetAttribute(bf16_gemm_dots<128, 64, 32>,
                             cudaFuncAttributeMaxDynamicSharedMemorySize, SMEM2);
    }

    const int nodeBlocks = (N_NODES + 255) / 256;
    const int nodeWarpBlocks = (N_NODES * 32 + 255) / 256;
    const int edgeBlocks = (E + 255) / 256;

    // ---- fork immediately: detect + CSR build on side stream, concurrent with gemm1 ----
    cudaEventRecord(ev_fork, 0);
    cudaStreamWaitEvent(s_side, ev_fork, 0);

    detect_idx_dtype_par<<<1, 128, 0, s_side>>>((const int*)ei);
    zero_counts<<<nodeBlocks, 256, 0, s_side>>>(cnt);
    count_edges<<<edgeBlocks, 256, 0, s_side>>>(ei, E, cnt);
    scan_block<<<NUM_SCAN_BLOCKS, SCAN_CHUNK, 0, s_side>>>(cnt, rowptr, bsum);
    scan_bsums<<<1, 128, 0, s_side>>>(bsum);
    add_offsets<<<nodeBlocks, 256, 0, s_side>>>(rowptr, bsum, cur, E);
    scatter_edges<<<edgeBlocks, 256, 0, s_side>>>(ei, E, cur, col);
    cudaEventRecord(ev_join, s_side);

    // ---- main stream: layer-1 GEMM with fused dots (dots stored, no atomics) ----
    {
        dim3 grid(1, (N_NODES + 127) / 128);
        bf16_gemm_dots<128, 128, 32><<<grid, 256, SMEM1>>>(x, W1, h1, as1, ad1, asrc, adst,
                                                           N_NODES, 128, 256);
    }

    // ---- join, then aggregate layer 1 ----
    cudaStreamWaitEvent(0, ev_join, 0);
    agg1<<<nodeWarpBlocks, 256>>>(rowptr, col, h1, asrc, adst, b1, hid);

    // ---- layer 2 ----
    {
        dim3 grid(1, (N_NODES + 127) / 128);
        bf16_gemm_dots<128, 64, 32><<<grid, 256, SMEM2>>>(hid, W2, h2, as2, ad2, asrc2, adst2,
                                                          N_NODES, 64, 128);
    }
    agg2<<<nodeWarpBlocks, 256>>>(rowptr, col, h2, asrc2, adst2, b2, out);
}

// round 14
// speedup vs baseline: 2.0614x; 1.1265x over previous
#include <cuda_runtime.h>
#include <cuda_bf16.h>
#include <cuda_fp16.h>
#include <math.h>
#include <stdint.h>

#define N_NODES 50000
#define NEG_SLOPE 0.2f
#define MAX_E 1200000
#define SCAN_CHUNK 512
#define NUM_SCAN_BLOCKS ((N_NODES + SCAN_CHUNK - 1) / SCAN_CHUNK)

// ---------------- device scratch (no allocs allowed) ----------------
__device__ __half g_h1 [(size_t)N_NODES * 128];   // fp16 gather operand, layer 1
__device__ float  g_hid[(size_t)N_NODES * 128];   // fp32 layer-2 GEMM input
__device__ __half g_h2 [(size_t)N_NODES * 64];    // fp16 gather operand, layer 2
__device__ float  g_asrc[N_NODES];
__device__ float  g_adst[N_NODES];
__device__ float  g_asrc2[N_NODES];
__device__ float  g_adst2[N_NODES];
__device__ int    g_cnt[N_NODES];
__device__ int    g_rowptr[N_NODES + 1];
__device__ int    g_cur[N_NODES];
__device__ int    g_col[MAX_E];
__device__ int    g_bsum[NUM_SCAN_BLOCKS + 1];
__device__ int    g_idx64;

__device__ __forceinline__ float leaky_exp(float e) {
    e = (e > 0.f) ? e : NEG_SLOPE * e;
    return __expf(e);
}

// ---------------- parallel dtype detection (int32 vs int64) ----------------
__global__ void detect_idx_dtype_par(const int* __restrict__ ei32) {
    __shared__ int nz;
    if (threadIdx.x == 0) nz = 0;
    __syncthreads();
    if (ei32[threadIdx.x * 2 + 1] != 0) atomicAdd(&nz, 1);
    __syncthreads();
    if (threadIdx.x == 0) g_idx64 = (nz == 0);
}

// ---------------- CSR build ----------------
__global__ void zero_counts(int* __restrict__ cnt) {
    int i = blockIdx.x * blockDim.x + threadIdx.x;
    if (i < N_NODES) cnt[i] = 0;
}

__global__ void count_edges(const void* __restrict__ ei, int E, int* __restrict__ cnt) {
    int i = blockIdx.x * blockDim.x + threadIdx.x;
    if (i >= E) return;
    int d;
    if (g_idx64) d = (int)((const long long*)ei)[(size_t)E + i];
    else         d = ((const int*)ei)[E + i];
    atomicAdd(cnt + d, 1);
}

__global__ void scan_block(const int* __restrict__ cnt, int* __restrict__ rowptr,
                           int* __restrict__ bsum) {
    __shared__ int sm[SCAN_CHUNK];
    int b = blockIdx.x, t = threadIdx.x;
    int i = b * SCAN_CHUNK + t;
    int v = (i < N_NODES) ? cnt[i] : 0;
    sm[t] = v;
    __syncthreads();
#pragma unroll
    for (int o = 1; o < SCAN_CHUNK; o <<= 1) {
        int x = (t >= o) ? sm[t - o] : 0;
        __syncthreads();
        sm[t] += x;
        __syncthreads();
    }
    if (i < N_NODES) rowptr[i] = sm[t] - v;  // exclusive
    if (t == SCAN_CHUNK - 1) bsum[b] = sm[t];
}

__global__ void scan_bsums(int* __restrict__ bsum) {
    __shared__ int sm[NUM_SCAN_BLOCKS];
    int t = threadIdx.x;
    if (t < NUM_SCAN_BLOCKS) sm[t] = bsum[t];
    __syncthreads();
    if (t == 0) {
        int acc = 0;
        for (int i = 0; i < NUM_SCAN_BLOCKS; i++) { int v = sm[i]; sm[i] = acc; acc += v; }
    }
    __syncthreads();
    if (t < NUM_SCAN_BLOCKS) bsum[t] = sm[t];
}

__global__ void add_offsets(int* __restrict__ rowptr, const int* __restrict__ bsum,
                            int* __restrict__ cur, int E) {
    int i = blockIdx.x * blockDim.x + threadIdx.x;
    if (i < N_NODES) {
        int r = rowptr[i] + bsum[i / SCAN_CHUNK];
        rowptr[i] = r;
        cur[i] = r;
    }
    if (i == 0) rowptr[N_NODES] = E;
}

__global__ void scatter_edges(const void* __restrict__ ei, int E,
                              int* __restrict__ cur, int* __restrict__ col) {
    int i = blockIdx.x * blockDim.x + threadIdx.x;
    if (i >= E) return;
    int s, d;
    if (g_idx64) {
        const long long* p = (const long long*)ei;
        s = (int)p[i];
        d = (int)p[(size_t)E + i];
    } else {
        const int* p = (const int*)ei;
        s = p[i];
        d = p[E + i];
    }
    int pos = atomicAdd(cur + d, 1);
    col[pos] = s;
}

// ---------------- single-term bf16 tensor-core GEMM + fused dots, cp.async pipelined ----------------
__device__ __forceinline__ uint32_t pack_bf16(float v0, float v1) {
    __nv_bfloat162 b2 = __floats2bfloat162_rn(v0, v1);
    return *reinterpret_cast<uint32_t*>(&b2);
}

__device__ __forceinline__ void mma_bf16(float* c, const uint32_t* a, const uint32_t* b) {
    asm volatile(
        "mma.sync.aligned.m16n8k16.row.col.f32.bf16.bf16.f32 "
        "{%0,%1,%2,%3}, {%4,%5,%6,%7}, {%8,%9}, {%0,%1,%2,%3};"
        : "+f"(c[0]), "+f"(c[1]), "+f"(c[2]), "+f"(c[3])
        : "r"(a[0]), "r"(a[1]), "r"(a[2]), "r"(a[3]), "r"(b[0]), "r"(b[1]));
}

__device__ __forceinline__ void cp_async16(uint32_t saddr, const void* gmem, int srcsize) {
    asm volatile("cp.async.ca.shared.global [%0], [%1], 16, %2;"
                 :: "r"(saddr), "l"(gmem), "r"(srcsize));
}
__device__ __forceinline__ void cp_commit() {
    asm volatile("cp.async.commit_group;");
}
__device__ __forceinline__ void cp_wait_all() {
    asm volatile("cp.async.wait_group 0;");
}

// A [M,K] row-major fp32, B [K,N] row-major fp32, C [M,N] fp16. BN==N (single block col).
// 8 warps, warp grid 4x2, 2-stage cp.async double buffer. Single bf16 MMA term
// (accuracy headroom measured: softmax attenuates ~50x; budget 220x).
// Epilogue: fp16 C store + per-row dots (smem block reduction, plain global store).
template <int BM, int BN, int BK>
__global__ void bf16_gemm_dots(const float* __restrict__ A, const float* __restrict__ B,
                               __half* __restrict__ C,
                               const float* __restrict__ att_s, const float* __restrict__ att_d,
                               float* __restrict__ asrc, float* __restrict__ adst,
                               int M, int N, int K) {
    constexpr int WR = 4, WC = 2;
    constexpr int nThreads = WR * WC * 32;
    constexpr int WM = BM / WR;          // 32
    constexpr int WN = BN / WC;          // 64 or 32
    constexpr int MT = WM / 16;          // 2
    constexpr int NT = WN / 8;           // 8 or 4
    constexpr int KS = BK / 16;          // 2
    constexpr int APAD = 4, BPAD = 8;
    constexpr int ASTRIDE = BK + APAD;
    constexpr int BSTRIDE = BN + BPAD;
    constexpr int A_BUF = BM * ASTRIDE;
    constexpr int B_BUF = BK * BSTRIDE;

    extern __shared__ float dynsmem[];
    float* Abase = dynsmem;              // [2][BM][ASTRIDE]
    float* Bbase = dynsmem + 2 * A_BUF;  // [2][BK][BSTRIDE]

    int tid = threadIdx.x;
    int wid = tid >> 5;
    int lane = tid & 31;
    int wr = wid / WC, wc = wid % WC;
    int row0 = blockIdx.y * BM;
    int grp = lane >> 2;
    int qd  = lane & 3;

    const int NIT = K / BK;

    auto prefetch = [&](int k0, int buf) {
        float* As = Abase + buf * A_BUF;
        float* Bs = Bbase + buf * B_BUF;
#pragma unroll
        for (int i = tid; i < BM * BK / 4; i += nThreads) {
            int r = i / (BK / 4);
            int c4 = i % (BK / 4);
            int gr = row0 + r;
            const float* src = A + ((gr < M) ? ((size_t)gr * K + k0 + c4 * 4) : 0);
            uint32_t sa = (uint32_t)__cvta_generic_to_shared(&As[r * ASTRIDE + c4 * 4]);
            cp_async16(sa, src, (gr < M) ? 16 : 0);
        }
#pragma unroll
        for (int i = tid; i < BK * BN / 4; i += nThreads) {
            int r = i / (BN / 4);
            int c4 = i % (BN / 4);
            const float* src = B + (size_t)(k0 + r) * N + c4 * 4;
            uint32_t sb = (uint32_t)__cvta_generic_to_shared(&Bs[r * BSTRIDE + c4 * 4]);
            cp_async16(sb, src, 16);
        }
        cp_commit();
    };

    float acc[MT][NT][4];
#pragma unroll
    for (int i = 0; i < MT; i++)
#pragma unroll
        for (int j = 0; j < NT; j++)
#pragma unroll
            for (int q = 0; q < 4; q++) acc[i][j][q] = 0.f;

    prefetch(0, 0);
    int buf = 0;

    for (int it = 0; it < NIT; it++) {
        cp_wait_all();
        __syncthreads();
        if (it + 1 < NIT) prefetch((it + 1) * BK, buf ^ 1);

        float* As = Abase + buf * A_BUF;
        float* Bs = Bbase + buf * B_BUF;

#pragma unroll
        for (int ks = 0; ks < KS; ks++) {
            int kc = ks * 16 + qd * 2;
            uint32_t afrag[MT][4];
#pragma unroll
            for (int mt = 0; mt < MT; mt++) {
                int rb = wr * WM + mt * 16 + grp;
                afrag[mt][0] = pack_bf16(As[rb * ASTRIDE + kc],           As[rb * ASTRIDE + kc + 1]);
                afrag[mt][1] = pack_bf16(As[(rb + 8) * ASTRIDE + kc],     As[(rb + 8) * ASTRIDE + kc + 1]);
                afrag[mt][2] = pack_bf16(As[rb * ASTRIDE + kc + 8],       As[rb * ASTRIDE + kc + 9]);
                afrag[mt][3] = pack_bf16(As[(rb + 8) * ASTRIDE + kc + 8], As[(rb + 8) * ASTRIDE + kc + 9]);
            }
#pragma unroll
            for (int nt = 0; nt < NT; nt++) {
                int n = wc * WN + nt * 8 + grp;
                int kb = ks * 16 + qd * 2;
                uint32_t bfrag[2];
                bfrag[0] = pack_bf16(Bs[kb * BSTRIDE + n],       Bs[(kb + 1) * BSTRIDE + n]);
                bfrag[1] = pack_bf16(Bs[(kb + 8) * BSTRIDE + n], Bs[(kb + 9) * BSTRIDE + n]);
#pragma unroll
                for (int mt = 0; mt < MT; mt++)
                    mma_bf16(acc[mt][nt], afrag[mt], bfrag);
            }
        }
        buf ^= 1;
    }

    // ---- epilogue: fp16 C store + dots via smem block reduction ----
    __syncthreads();                 // all compute done; smem reusable
    float* ssm = dynsmem;            // [BM]
    float* sdm = dynsmem + BM;       // [BM]
    if (tid < BM) { ssm[tid] = 0.f; sdm[tid] = 0.f; }
    __syncthreads();

    float ss[MT][2], sd[MT][2];
#pragma unroll
    for (int mt = 0; mt < MT; mt++) { ss[mt][0] = ss[mt][1] = sd[mt][0] = sd[mt][1] = 0.f; }

#pragma unroll
    for (int mt = 0; mt < MT; mt++) {
#pragma unroll
        for (int nt = 0; nt < NT; nt++) {
            int row = row0 + wr * WM + mt * 16 + grp;
            int col = wc * WN + nt * 8 + qd * 2;
            if (row < M)
                *(__half2*)(C + (size_t)row * N + col) =
                    __floats2half2_rn(acc[mt][nt][0], acc[mt][nt][1]);
            if (row + 8 < M)
                *(__half2*)(C + (size_t)(row + 8) * N + col) =
                    __floats2half2_rn(acc[mt][nt][2], acc[mt][nt][3]);

            float a0 = att_s[col], a1 = att_s[col + 1];
            float d0 = att_d[col], d1 = att_d[col + 1];
            ss[mt][0] += acc[mt][nt][0] * a0 + acc[mt][nt][1] * a1;
            ss[mt][1] += acc[mt][nt][2] * a0 + acc[mt][nt][3] * a1;
            sd[mt][0] += acc[mt][nt][0] * d0 + acc[mt][nt][1] * d1;
            sd[mt][1] += acc[mt][nt][2] * d0 + acc[mt][nt][3] * d1;
        }
    }
#pragma unroll
    for (int mt = 0; mt < MT; mt++) {
#pragma unroll
        for (int h = 0; h < 2; h++) {
            float vs = ss[mt][h], vd = sd[mt][h];
            vs += __shfl_xor_sync(0xffffffffu, vs, 1);
            vs += __shfl_xor_sync(0xffffffffu, vs, 2);
            vd += __shfl_xor_sync(0xffffffffu, vd, 1);
            vd += __shfl_xor_sync(0xffffffffu, vd, 2);
            if (qd == 0) {
                int rl = wr * WM + mt * 16 + grp + h * 8;
                atomicAdd(&ssm[rl], vs);
                atomicAdd(&sdm[rl], vd);
            }
        }
    }
    __syncthreads();
    if (tid < BM) {
        int row = row0 + tid;
        if (row < M) { asrc[row] = ssm[tid]; adst[row] = sdm[tid]; }
    }
}

// ---------------- fused gather-aggregate layer 1 (C=128, fp16 h): softmax + bias + ReLU ----------------
__global__ void agg1(const int* __restrict__ rowptr, const int* __restrict__ col,
                     const __half* __restrict__ h, const float* __restrict__ asrc,
                     const float* __restrict__ adst, const float* __restrict__ bias,
                     float* __restrict__ out) {
    int warp = (blockIdx.x * blockDim.x + threadIdx.x) >> 5;
    int lane = threadIdx.x & 31;
    if (warp >= N_NODES) return;
    int d = warp;
    float ad = adst[d];

    float ee = leaky_exp(asrc[d] + ad);
    uint2 u = ((const uint2*)(h + (size_t)d * 128))[lane];
    float2 p0 = __half22float2(*(__half2*)&u.x);
    float2 p1 = __half22float2(*(__half2*)&u.y);
    float ax = p0.x * ee, ay = p0.y * ee, az = p1.x * ee, aw = p1.y * ee;
    float denom = ee;

    int beg = rowptr[d], end = rowptr[d + 1];
    for (int j0 = beg; j0 < end; j0 += 32) {
        int idx = j0 + lane;
        int sj = 0;
        float aj = 0.f;
        if (idx < end) { sj = col[idx]; aj = asrc[sj]; }
        int cnt = min(32, end - j0);
#pragma unroll 4
        for (int j = 0; j < cnt; j++) {
            int s = __shfl_sync(0xffffffffu, sj, j);
            float a = __shfl_sync(0xffffffffu, aj, j);
            float w = leaky_exp(a + ad);
            uint2 ux = ((const uint2*)(h + (size_t)s * 128))[lane];
            float2 x0 = __half22float2(*(__half2*)&ux.x);
            float2 x1 = __half22float2(*(__half2*)&ux.y);
            ax += w * x0.x; ay += w * x0.y; az += w * x1.x; aw += w * x1.y;
            denom += w;
        }
    }
    float inv = 1.f / denom;
    float4 b4 = ((const float4*)bias)[lane];
    float4 o;
    o.x = fmaxf(ax * inv + b4.x, 0.f);
    o.y = fmaxf(ay * inv + b4.y, 0.f);
    o.z = fmaxf(az * inv + b4.z, 0.f);
    o.w = fmaxf(aw * inv + b4.w, 0.f);
    ((float4*)(out + (size_t)d * 128))[lane] = o;
}

// ---------------- fused gather-aggregate layer 2 (C=64, fp16 h): softmax + bias + log_softmax ----------------
__global__ void agg2(const int* __restrict__ rowptr, const int* __restrict__ col,
                     const __half* __restrict__ h, const float* __restrict__ asrc,
                     const float* __restrict__ adst, const float* __restrict__ bias,
                     float* __restrict__ out) {
    int warp = (blockIdx.x * blockDim.x + threadIdx.x) >> 5;
    int lane = threadIdx.x & 31;
    if (warp >= N_NODES) return;
    int d = warp;
    float ad = adst[d];

    float ee = leaky_exp(asrc[d] + ad);
    float2 hv = __half22float2(((const __half2*)(h + (size_t)d * 64))[lane]);
    float ax = hv.x * ee, ay = hv.y * ee;
    float denom = ee;

    int beg = rowptr[d], end = rowptr[d + 1];
    for (int j0 = beg; j0 < end; j0 += 32) {
        int idx = j0 + lane;
        int sj = 0;
        float aj = 0.f;
        if (idx < end) { sj = col[idx]; aj = asrc[sj]; }
        int cnt = min(32, end - j0);
#pragma unroll 4
        for (int j = 0; j < cnt; j++) {
            int s = __shfl_sync(0xffffffffu, sj, j);
            float a = __shfl_sync(0xffffffffu, aj, j);
            float w = leaky_exp(a + ad);
            float2 x = __half22float2(((const __half2*)(h + (size_t)s * 64))[lane]);
            ax += w * x.x; ay += w * x.y;
            denom += w;
        }
    }
    float inv = 1.f / denom;
    float2 b2 = ((const float2*)bias)[lane];
    float v0 = ax * inv + b2.x;
    float v1 = ay * inv + b2.y;
    float m = fmaxf(v0, v1);
#pragma unroll
    for (int o = 16; o > 0; o >>= 1) m = fmaxf(m, __shfl_xor_sync(0xffffffffu, m, o));
    float sm = __expf(v0 - m) + __expf(v1 - m);
#pragma unroll
    for (int o = 16; o > 0; o >>= 1) sm += __shfl_xor_sync(0xffffffffu, sm, o);
    float lse = m + logf(sm);
    float2 o2;
    o2.x = v0 - lse;
    o2.y = v1 - lse;
    ((float2*)(out + (size_t)d * 64))[lane] = o2;
}

// ---------------- host orchestration ----------------
extern "C" void kernel_launch(void* const* d_in, const int* in_sizes, int n_in,
                              void* d_out, int out_size) {
    const float* x   = (const float*)d_in[0];
    const void*  ei  = d_in[1];
    const float* W1  = (const float*)d_in[2];
    const float* as1 = (const float*)d_in[3];
    const float* ad1 = (const float*)d_in[4];
    const float* b1  = (const float*)d_in[5];
    const float* W2  = (const float*)d_in[6];
    const float* as2 = (const float*)d_in[7];
    const float* ad2 = (const float*)d_in[8];
    const float* b2  = (const float*)d_in[9];
    float* out = (float*)d_out;

    int E = in_sizes[1] / 2;

    __half *h1, *h2;
    float *hid, *asrc, *adst, *asrc2, *adst2;
    int *cnt, *rowptr, *cur, *col, *bsum;
    cudaGetSymbolAddress((void**)&h1,  g_h1);
    cudaGetSymbolAddress((void**)&hid, g_hid);
    cudaGetSymbolAddress((void**)&h2,  g_h2);
    cudaGetSymbolAddress((void**)&asrc, g_asrc);
    cudaGetSymbolAddress((void**)&adst, g_adst);
    cudaGetSymbolAddress((void**)&asrc2, g_asrc2);
    cudaGetSymbolAddress((void**)&adst2, g_adst2);
    cudaGetSymbolAddress((void**)&cnt, g_cnt);
    cudaGetSymbolAddress((void**)&rowptr, g_rowptr);
    cudaGetSymbolAddress((void**)&cur, g_cur);
    cudaGetSymbolAddress((void**)&col, g_col);
    cudaGetSymbolAddress((void**)&bsum, g_bsum);

    const int SMEM1 = (2 * 128 * (32 + 4) + 2 * 32 * (128 + 8)) * 4;  // 71680
    const int SMEM2 = (2 * 128 * (32 + 4) + 2 * 32 * (64 + 8)) * 4;   // 55296

    static cudaStream_t s_side = nullptr;
    static cudaEvent_t ev_fork = nullptr, ev_join = nullptr;
    if (!s_side) {
        cudaStreamCreateWithFlags(&s_side, cudaStreamNonBlocking);
        cudaEventCreateWithFlags(&ev_fork, cudaEventDisableTiming);
        cudaEventCreateWithFlags(&ev_join, cudaEventDisableTiming);
        cudaFuncSetAttribute(bf16_gemm_dots<128, 128, 32>,
                             cudaFuncAttributeMaxDynamicSharedMemorySize, SMEM1);
        cudaFuncSetAttribute(bf16_gemm_dots<128, 64, 32>,
                             cudaFuncAttributeMaxDynamicSharedMemorySize, SMEM2);
    }

    const int nodeBlocks = (N_NODES + 255) / 256;
    const int nodeWarpBlocks = (N_NODES * 32 + 255) / 256;
    const int edgeBlocks = (E + 255) / 256;

    // ---- fork immediately: detect + CSR build on side stream, concurrent with gemm1 ----
    cudaEventRecord(ev_fork, 0);
    cudaStreamWaitEvent(s_side, ev_fork, 0);

    detect_idx_dtype_par<<<1, 128, 0, s_side>>>((const int*)ei);
    zero_counts<<<nodeBlocks, 256, 0, s_side>>>(cnt);
    count_edges<<<edgeBlocks, 256, 0, s_side>>>(ei, E, cnt);
    scan_block<<<NUM_SCAN_BLOCKS, SCAN_CHUNK, 0, s_side>>>(cnt, rowptr, bsum);
    scan_bsums<<<1, 128, 0, s_side>>>(bsum);
    add_offsets<<<nodeBlocks, 256, 0, s_side>>>(rowptr, bsum, cur, E);
    scatter_edges<<<edgeBlocks, 256, 0, s_side>>>(ei, E, cur, col);
    cudaEventRecord(ev_join, s_side);

    // ---- main stream: layer-1 GEMM with fused dots ----
    {
        dim3 grid(1, (N_NODES + 127) / 128);
        bf16_gemm_dots<128, 128, 32><<<grid, 256, SMEM1>>>(x, W1, h1, as1, ad1, asrc, adst,
                                                           N_NODES, 128, 256);
    }

    // ---- join, then aggregate layer 1 ----
    cudaStreamWaitEvent(0, ev_join, 0);
    agg1<<<nodeWarpBlocks, 256>>>(rowptr, col, h1, asrc, adst, b1, hid);

    // ---- layer 2 ----
    {
        dim3 grid(1, (N_NODES + 127) / 128);
        bf16_gemm_dots<128, 64, 32><<<grid, 256, SMEM2>>>(hid, W2, h2, as2, ad2, asrc2, adst2,
                                                          N_NODES, 64, 128);
    }
    agg2<<<nodeWarpBlocks, 256>>>(rowptr, col, h2, asrc2, adst2, b2, out);
}

// round 15
// speedup vs baseline: 2.1587x; 1.0472x over previous
#include <cuda_runtime.h>
#include <cuda_bf16.h>
#include <cuda_fp16.h>
#include <math.h>
#include <stdint.h>

#define N_NODES 50000
#define NEG_SLOPE 0.2f
#define MAX_E 1200000
#define SCAN_CHUNK 512
#define NUM_SCAN_BLOCKS ((N_NODES + SCAN_CHUNK - 1) / SCAN_CHUNK)

// ---------------- device scratch (no allocs allowed) ----------------
__device__ __half g_h1 [(size_t)N_NODES * 128];   // fp16 gather operand, layer 1
__device__ float  g_hid[(size_t)N_NODES * 128];   // fp32 layer-2 GEMM input
__device__ __half g_h2 [(size_t)N_NODES * 64];    // fp16 gather operand, layer 2
__device__ float  g_asrc[N_NODES];
__device__ float  g_adst[N_NODES];
__device__ float  g_asrc2[N_NODES];
__device__ float  g_adst2[N_NODES];
__device__ int    g_cnt[N_NODES];
__device__ int    g_rowptr[N_NODES + 1];
__device__ int    g_cur[N_NODES];
__device__ int    g_col[MAX_E];
__device__ int    g_bsum[NUM_SCAN_BLOCKS + 1];
__device__ int    g_idx64;

__device__ __forceinline__ float leaky_exp(float e) {
    e = (e > 0.f) ? e : NEG_SLOPE * e;
    return __expf(e);
}

// ---------------- parallel dtype detection (int32 vs int64) ----------------
__global__ void detect_idx_dtype_par(const int* __restrict__ ei32) {
    __shared__ int nz;
    if (threadIdx.x == 0) nz = 0;
    __syncthreads();
    if (ei32[threadIdx.x * 2 + 1] != 0) atomicAdd(&nz, 1);
    __syncthreads();
    if (threadIdx.x == 0) g_idx64 = (nz == 0);
}

// ---------------- CSR build ----------------
__global__ void zero_counts(int* __restrict__ cnt) {
    int i = blockIdx.x * blockDim.x + threadIdx.x;
    if (i < N_NODES) cnt[i] = 0;
}

__global__ void count_edges(const void* __restrict__ ei, int E, int* __restrict__ cnt) {
    int i = blockIdx.x * blockDim.x + threadIdx.x;
    if (i >= E) return;
    int d;
    if (g_idx64) d = (int)((const long long*)ei)[(size_t)E + i];
    else         d = ((const int*)ei)[E + i];
    atomicAdd(cnt + d, 1);
}

__global__ void scan_block(const int* __restrict__ cnt, int* __restrict__ rowptr,
                           int* __restrict__ bsum) {
    __shared__ int sm[SCAN_CHUNK];
    int b = blockIdx.x, t = threadIdx.x;
    int i = b * SCAN_CHUNK + t;
    int v = (i < N_NODES) ? cnt[i] : 0;
    sm[t] = v;
    __syncthreads();
#pragma unroll
    for (int o = 1; o < SCAN_CHUNK; o <<= 1) {
        int x = (t >= o) ? sm[t - o] : 0;
        __syncthreads();
        sm[t] += x;
        __syncthreads();
    }
    if (i < N_NODES) rowptr[i] = sm[t] - v;  // exclusive
    if (t == SCAN_CHUNK - 1) bsum[b] = sm[t];
}

__global__ void scan_bsums(int* __restrict__ bsum) {
    __shared__ int sm[NUM_SCAN_BLOCKS];
    int t = threadIdx.x;
    if (t < NUM_SCAN_BLOCKS) sm[t] = bsum[t];
    __syncthreads();
    if (t == 0) {
        int acc = 0;
        for (int i = 0; i < NUM_SCAN_BLOCKS; i++) { int v = sm[i]; sm[i] = acc; acc += v; }
    }
    __syncthreads();
    if (t < NUM_SCAN_BLOCKS) bsum[t] = sm[t];
}

__global__ void add_offsets(int* __restrict__ rowptr, const int* __restrict__ bsum,
                            int* __restrict__ cur, int E) {
    int i = blockIdx.x * blockDim.x + threadIdx.x;
    if (i < N_NODES) {
        int r = rowptr[i] + bsum[i / SCAN_CHUNK];
        rowptr[i] = r;
        cur[i] = r;
    }
    if (i == 0) rowptr[N_NODES] = E;
}

__global__ void scatter_edges(const void* __restrict__ ei, int E,
                              int* __restrict__ cur, int* __restrict__ col) {
    int i = blockIdx.x * blockDim.x + threadIdx.x;
    if (i >= E) return;
    int s, d;
    if (g_idx64) {
        const long long* p = (const long long*)ei;
        s = (int)p[i];
        d = (int)p[(size_t)E + i];
    } else {
        const int* p = (const int*)ei;
        s = p[i];
        d = p[E + i];
    }
    int pos = atomicAdd(cur + d, 1);
    col[pos] = s;
}

// ---------------- single-term bf16 GEMM, bf16 smem tiles + register-staged pipeline ----------------
__device__ __forceinline__ uint32_t pack_bf16(float v0, float v1) {
    __nv_bfloat162 b2 = __floats2bfloat162_rn(v0, v1);
    return *reinterpret_cast<uint32_t*>(&b2);
}

__device__ __forceinline__ void mma_bf16(float* c, const uint32_t* a, const uint32_t* b) {
    asm volatile(
        "mma.sync.aligned.m16n8k16.row.col.f32.bf16.bf16.f32 "
        "{%0,%1,%2,%3}, {%4,%5,%6,%7}, {%8,%9}, {%0,%1,%2,%3};"
        : "+f"(c[0]), "+f"(c[1]), "+f"(c[2]), "+f"(c[3])
        : "r"(a[0]), "r"(a[1]), "r"(a[2]), "r"(a[3]), "r"(b[0]), "r"(b[1]));
}

// A [M,K] row-major fp32, B [K,N] row-major fp32, C [M,N] fp16. BN==N (single block col).
// smem: A tile [BM][BK] bf16 (APAD), B tile TRANSPOSED [BN][BK] bf16 (BPAD).
// Global fp32 staged in registers for tile t+1 while computing tile t.
// Epilogue: fp16 C store + per-row dots (smem block reduction, plain store).
template <int BM, int BN, int BK>
__global__ void bf16_gemm_dots(const float* __restrict__ A, const float* __restrict__ B,
                               __half* __restrict__ C,
                               const float* __restrict__ att_s, const float* __restrict__ att_d,
                               float* __restrict__ asrc, float* __restrict__ adst,
                               int M, int N, int K) {
    constexpr int WR = 4, WC = 2;
    constexpr int nThreads = WR * WC * 32;
    constexpr int WM = BM / WR;          // 32
    constexpr int WN = BN / WC;          // 64 or 32
    constexpr int MT = WM / 16;          // 2
    constexpr int NT = WN / 8;           // 8 or 4
    constexpr int KS = BK / 16;          // 2
    constexpr int AS = BK + 2;           // 34 bf16 (17 words/row -> coprime with 32 banks)
    constexpr int BS = BK + 6;           // 38 bf16 (19 words/row -> coprime with 32 banks)
    constexpr int A4  = BM * BK / (4 * nThreads);          // float4 A loads per thread (4)
    constexpr int BQN = (BK / 2) * (BN / 4) / nThreads;    // B quads per thread (2 or 1)

    extern __shared__ char smemraw[];
    __nv_bfloat16* As = (__nv_bfloat16*)smemraw;                 // [BM][AS]
    __nv_bfloat16* Bs = (__nv_bfloat16*)smemraw + BM * AS;       // [BN][BS]

    int tid = threadIdx.x;
    int wid = tid >> 5;
    int lane = tid & 31;
    int wr = wid / WC, wc = wid % WC;
    int row0 = blockIdx.y * BM;
    int grp = lane >> 2;
    int qd  = lane & 3;

    const int NIT = K / BK;

    float4 aR[A4];
    float4 bR0[BQN], bR1[BQN];

    auto loadRegs = [&](int k0) {
#pragma unroll
        for (int p = 0; p < A4; p++) {
            int i = tid + p * nThreads;
            int r = i / (BK / 4), c4 = i % (BK / 4);
            int gr = row0 + r;
            aR[p] = (gr < M) ? *(const float4*)(A + (size_t)gr * K + k0 + c4 * 4)
                             : make_float4(0.f, 0.f, 0.f, 0.f);
        }
#pragma unroll
        for (int p = 0; p < BQN; p++) {
            int i = tid + p * nThreads;
            int qn = i % (BN / 4), qk = i / (BN / 4);
            int k = qk * 2, n = qn * 4;
            bR0[p] = *(const float4*)(B + (size_t)(k0 + k) * N + n);
            bR1[p] = *(const float4*)(B + (size_t)(k0 + k + 1) * N + n);
        }
    };

    auto storeTiles = [&]() {
#pragma unroll
        for (int p = 0; p < A4; p++) {
            int i = tid + p * nThreads;
            int r = i / (BK / 4), c4 = i % (BK / 4);
            *(uint32_t*)&As[r * AS + c4 * 4]     = pack_bf16(aR[p].x, aR[p].y);
            *(uint32_t*)&As[r * AS + c4 * 4 + 2] = pack_bf16(aR[p].z, aR[p].w);
        }
#pragma unroll
        for (int p = 0; p < BQN; p++) {
            int i = tid + p * nThreads;
            int qn = i % (BN / 4), qk = i / (BN / 4);
            int k = qk * 2, n = qn * 4;
            const float* r0 = &bR0[p].x;
            const float* r1 = &bR1[p].x;
#pragma unroll
            for (int j = 0; j < 4; j++)
                *(uint32_t*)&Bs[(n + j) * BS + k] = pack_bf16(r0[j], r1[j]);
        }
    };

    float acc[MT][NT][4];
#pragma unroll
    for (int i = 0; i < MT; i++)
#pragma unroll
        for (int j = 0; j < NT; j++)
#pragma unroll
            for (int q = 0; q < 4; q++) acc[i][j][q] = 0.f;

    loadRegs(0);

    for (int it = 0; it < NIT; it++) {
        storeTiles();
        __syncthreads();
        if (it + 1 < NIT) loadRegs((it + 1) * BK);   // global loads overlap compute below

#pragma unroll
        for (int ks = 0; ks < KS; ks++) {
            int kc = ks * 16 + qd * 2;
            uint32_t afrag[MT][4];
#pragma unroll
            for (int mt = 0; mt < MT; mt++) {
                int rb = wr * WM + mt * 16 + grp;
                afrag[mt][0] = *(const uint32_t*)&As[rb * AS + kc];
                afrag[mt][1] = *(const uint32_t*)&As[(rb + 8) * AS + kc];
                afrag[mt][2] = *(const uint32_t*)&As[rb * AS + kc + 8];
                afrag[mt][3] = *(const uint32_t*)&As[(rb + 8) * AS + kc + 8];
            }
#pragma unroll
            for (int nt = 0; nt < NT; nt++) {
                int n = wc * WN + nt * 8 + grp;
                uint32_t bfrag[2];
                bfrag[0] = *(const uint32_t*)&Bs[n * BS + kc];
                bfrag[1] = *(const uint32_t*)&Bs[n * BS + kc + 8];
#pragma unroll
                for (int mt = 0; mt < MT; mt++)
                    mma_bf16(acc[mt][nt], afrag[mt], bfrag);
            }
        }
        __syncthreads();
    }

    // ---- epilogue: fp16 C store + dots via smem block reduction ----
    float* ssm = (float*)smemraw;        // [BM]
    float* sdm = (float*)smemraw + BM;   // [BM]
    if (tid < BM) { ssm[tid] = 0.f; sdm[tid] = 0.f; }
    __syncthreads();

    float ss[MT][2], sd[MT][2];
#pragma unroll
    for (int mt = 0; mt < MT; mt++) { ss[mt][0] = ss[mt][1] = sd[mt][0] = sd[mt][1] = 0.f; }

#pragma unroll
    for (int mt = 0; mt < MT; mt++) {
#pragma unroll
        for (int nt = 0; nt < NT; nt++) {
            int row = row0 + wr * WM + mt * 16 + grp;
            int col = wc * WN + nt * 8 + qd * 2;
            if (row < M)
                *(__half2*)(C + (size_t)row * N + col) =
                    __floats2half2_rn(acc[mt][nt][0], acc[mt][nt][1]);
            if (row + 8 < M)
                *(__half2*)(C + (size_t)(row + 8) * N + col) =
                    __floats2half2_rn(acc[mt][nt][2], acc[mt][nt][3]);

            float a0 = att_s[col], a1 = att_s[col + 1];
            float d0 = att_d[col], d1 = att_d[col + 1];
            ss[mt][0] += acc[mt][nt][0] * a0 + acc[mt][nt][1] * a1;
            ss[mt][1] += acc[mt][nt][2] * a0 + acc[mt][nt][3] * a1;
            sd[mt][0] += acc[mt][nt][0] * d0 + acc[mt][nt][1] * d1;
            sd[mt][1] += acc[mt][nt][2] * d0 + acc[mt][nt][3] * d1;
        }
    }
#pragma unroll
    for (int mt = 0; mt < MT; mt++) {
#pragma unroll
        for (int h = 0; h < 2; h++) {
            float vs = ss[mt][h], vd = sd[mt][h];
            vs += __shfl_xor_sync(0xffffffffu, vs, 1);
            vs += __shfl_xor_sync(0xffffffffu, vs, 2);
            vd += __shfl_xor_sync(0xffffffffu, vd, 1);
            vd += __shfl_xor_sync(0xffffffffu, vd, 2);
            if (qd == 0) {
                int rl = wr * WM + mt * 16 + grp + h * 8;
                atomicAdd(&ssm[rl], vs);
                atomicAdd(&sdm[rl], vd);
            }
        }
    }
    __syncthreads();
    if (tid < BM) {
        int row = row0 + tid;
        if (row < M) { asrc[row] = ssm[tid]; adst[row] = sdm[tid]; }
    }
}

// ---------------- fused gather-aggregate layer 1 (C=128, fp16 h): softmax + bias + ReLU ----------------
__global__ void agg1(const int* __restrict__ rowptr, const int* __restrict__ col,
                     const __half* __restrict__ h, const float* __restrict__ asrc,
                     const float* __restrict__ adst, const float* __restrict__ bias,
                     float* __restrict__ out) {
    int warp = (blockIdx.x * blockDim.x + threadIdx.x) >> 5;
    int lane = threadIdx.x & 31;
    if (warp >= N_NODES) return;
    int d = warp;
    float ad = adst[d];

    float ee = leaky_exp(asrc[d] + ad);
    uint2 u = ((const uint2*)(h + (size_t)d * 128))[lane];
    float2 p0 = __half22float2(*(__half2*)&u.x);
    float2 p1 = __half22float2(*(__half2*)&u.y);
    float ax = p0.x * ee, ay = p0.y * ee, az = p1.x * ee, aw = p1.y * ee;
    float denom = ee;

    int beg = rowptr[d], end = rowptr[d + 1];
    for (int j0 = beg; j0 < end; j0 += 32) {
        int idx = j0 + lane;
        int sj = 0;
        float aj = 0.f;
        if (idx < end) { sj = col[idx]; aj = asrc[sj]; }
        int cnt = min(32, end - j0);
#pragma unroll 4
        for (int j = 0; j < cnt; j++) {
            int s = __shfl_sync(0xffffffffu, sj, j);
            float a = __shfl_sync(0xffffffffu, aj, j);
            float w = leaky_exp(a + ad);
            uint2 ux = ((const uint2*)(h + (size_t)s * 128))[lane];
            float2 x0 = __half22float2(*(__half2*)&ux.x);
            float2 x1 = __half22float2(*(__half2*)&ux.y);
            ax += w * x0.x; ay += w * x0.y; az += w * x1.x; aw += w * x1.y;
            denom += w;
        }
    }
    float inv = 1.f / denom;
    float4 b4 = ((const float4*)bias)[lane];
    float4 o;
    o.x = fmaxf(ax * inv + b4.x, 0.f);
    o.y = fmaxf(ay * inv + b4.y, 0.f);
    o.z = fmaxf(az * inv + b4.z, 0.f);
    o.w = fmaxf(aw * inv + b4.w, 0.f);
    ((float4*)(out + (size_t)d * 128))[lane] = o;
}

// ---------------- fused gather-aggregate layer 2 (C=64, fp16 h): softmax + bias + log_softmax ----------------
__global__ void agg2(const int* __restrict__ rowptr, const int* __restrict__ col,
                     const __half* __restrict__ h, const float* __restrict__ asrc,
                     const float* __restrict__ adst, const float* __restrict__ bias,
                     float* __restrict__ out) {
    int warp = (blockIdx.x * blockDim.x + threadIdx.x) >> 5;
    int lane = threadIdx.x & 31;
    if (warp >= N_NODES) return;
    int d = warp;
    float ad = adst[d];

    float ee = leaky_exp(asrc[d] + ad);
    float2 hv = __half22float2(((const __half2*)(h + (size_t)d * 64))[lane]);
    float ax = hv.x * ee, ay = hv.y * ee;
    float denom = ee;

    int beg = rowptr[d], end = rowptr[d + 1];
    for (int j0 = beg; j0 < end; j0 += 32) {
        int idx = j0 + lane;
        int sj = 0;
        float aj = 0.f;
        if (idx < end) { sj = col[idx]; aj = asrc[sj]; }
        int cnt = min(32, end - j0);
#pragma unroll 4
        for (int j = 0; j < cnt; j++) {
            int s = __shfl_sync(0xffffffffu, sj, j);
            float a = __shfl_sync(0xffffffffu, aj, j);
            float w = leaky_exp(a + ad);
            float2 x = __half22float2(((const __half2*)(h + (size_t)s * 64))[lane]);
            ax += w * x.x; ay += w * x.y;
            denom += w;
        }
    }
    float inv = 1.f / denom;
    float2 b2 = ((const float2*)bias)[lane];
    float v0 = ax * inv + b2.x;
    float v1 = ay * inv + b2.y;
    float m = fmaxf(v0, v1);
#pragma unroll
    for (int o = 16; o > 0; o >>= 1) m = fmaxf(m, __shfl_xor_sync(0xffffffffu, m, o));
    float sm = __expf(v0 - m) + __expf(v1 - m);
#pragma unroll
    for (int o = 16; o > 0; o >>= 1) sm += __shfl_xor_sync(0xffffffffu, sm, o);
    float lse = m + logf(sm);
    float2 o2;
    o2.x = v0 - lse;
    o2.y = v1 - lse;
    ((float2*)(out + (size_t)d * 64))[lane] = o2;
}

// ---------------- host orchestration ----------------
extern "C" void kernel_launch(void* const* d_in, const int* in_sizes, int n_in,
                              void* d_out, int out_size) {
    const float* x   = (const float*)d_in[0];
    const void*  ei  = d_in[1];
    const float* W1  = (const float*)d_in[2];
    const float* as1 = (const float*)d_in[3];
    const float* ad1 = (const float*)d_in[4];
    const float* b1  = (const float*)d_in[5];
    const float* W2  = (const float*)d_in[6];
    const float* as2 = (const float*)d_in[7];
    const float* ad2 = (const float*)d_in[8];
    const float* b2  = (const float*)d_in[9];
    float* out = (float*)d_out;

    int E = in_sizes[1] / 2;

    __half *h1, *h2;
    float *hid, *asrc, *adst, *asrc2, *adst2;
    int *cnt, *rowptr, *cur, *col, *bsum;
    cudaGetSymbolAddress((void**)&h1,  g_h1);
    cudaGetSymbolAddress((void**)&hid, g_hid);
    cudaGetSymbolAddress((void**)&h2,  g_h2);
    cudaGetSymbolAddress((void**)&asrc, g_asrc);
    cudaGetSymbolAddress((void**)&adst, g_adst);
    cudaGetSymbolAddress((void**)&asrc2, g_asrc2);
    cudaGetSymbolAddress((void**)&adst2, g_adst2);
    cudaGetSymbolAddress((void**)&cnt, g_cnt);
    cudaGetSymbolAddress((void**)&rowptr, g_rowptr);
    cudaGetSymbolAddress((void**)&cur, g_cur);
    cudaGetSymbolAddress((void**)&col, g_col);
    cudaGetSymbolAddress((void**)&bsum, g_bsum);

    // bf16 smem tiles: A [BM][BK+2], B [BN][BK+6]
    const int SMEM1 = (128 * 34 + 128 * 38) * 2;  // 18432 B
    const int SMEM2 = (128 * 34 + 64 * 38) * 2;   // 13568 B

    static cudaStream_t s_side = nullptr;
    static cudaEvent_t ev_fork = nullptr, ev_join = nullptr;
    if (!s_side) {
        cudaStreamCreateWithFlags(&s_side, cudaStreamNonBlocking);
        cudaEventCreateWithFlags(&ev_fork, cudaEventDisableTiming);
        cudaEventCreateWithFlags(&ev_join, cudaEventDisableTiming);
    }

    const int nodeBlocks = (N_NODES + 255) / 256;
    const int nodeWarpBlocks = (N_NODES * 32 + 255) / 256;
    const int edgeBlocks = (E + 255) / 256;

    // ---- fork immediately: detect + CSR build on side stream, concurrent with gemm1 ----
    cudaEventRecord(ev_fork, 0);
    cudaStreamWaitEvent(s_side, ev_fork, 0);

    detect_idx_dtype_par<<<1, 128, 0, s_side>>>((const int*)ei);
    zero_counts<<<nodeBlocks, 256, 0, s_side>>>(cnt);
    count_edges<<<edgeBlocks, 256, 0, s_side>>>(ei, E, cnt);
    scan_block<<<NUM_SCAN_BLOCKS, SCAN_CHUNK, 0, s_side>>>(cnt, rowptr, bsum);
    scan_bsums<<<1, 128, 0, s_side>>>(bsum);
    add_offsets<<<nodeBlocks, 256, 0, s_side>>>(rowptr, bsum, cur, E);
    scatter_edges<<<edgeBlocks, 256, 0, s_side>>>(ei, E, cur, col);
    cudaEventRecord(ev_join, s_side);

    // ---- main stream: layer-1 GEMM with fused dots ----
    {
        dim3 grid(1, (N_NODES + 127) / 128);
        bf16_gemm_dots<128, 128, 32><<<grid, 256, SMEM1>>>(x, W1, h1, as1, ad1, asrc, adst,
                                                           N_NODES, 128, 256);
    }

    // ---- join, then aggregate layer 1 ----
    cudaStreamWaitEvent(0, ev_join, 0);
    agg1<<<nodeWarpBlocks, 256>>>(rowptr, col, h1, asrc, adst, b1, hid);

    // ---- layer 2 ----
    {
        dim3 grid(1, (N_NODES + 127) / 128);
        bf16_gemm_dots<128, 64, 32><<<grid, 256, SMEM2>>>(hid, W2, h2, as2, ad2, asrc2, adst2,
                                                          N_NODES, 64, 128);
    }
    agg2<<<nodeWarpBlocks, 256>>>(rowptr, col, h2, asrc2, adst2, b2, out);
}

// round 17
// speedup vs baseline: 2.2027x; 1.0204x over previous
#include <cuda_runtime.h>
#include <cuda_bf16.h>
#include <cuda_fp16.h>
#include <math.h>
#include <stdint.h>

#define N_NODES 50000
#define NEG_SLOPE 0.2f
#define MAX_E 1200000
#define SCAN_CHUNK 512
#define NUM_SCAN_BLOCKS ((N_NODES + SCAN_CHUNK - 1) / SCAN_CHUNK)

// ---------------- device scratch (no allocs allowed) ----------------
__device__ __half g_h1 [(size_t)N_NODES * 128];   // fp16 gather operand, layer 1
__device__ float  g_hid[(size_t)N_NODES * 128];   // fp32 layer-2 GEMM input
__device__ __half g_h2 [(size_t)N_NODES * 64];    // fp16 gather operand, layer 2
__device__ float  g_asrc[N_NODES];
__device__ float  g_adst[N_NODES];
__device__ float  g_asrc2[N_NODES];
__device__ float  g_adst2[N_NODES];
__device__ int    g_cnt[N_NODES];
__device__ int    g_rowptr[N_NODES + 1];
__device__ int    g_cur[N_NODES];
__device__ int    g_col[MAX_E];
__device__ int    g_bsum[NUM_SCAN_BLOCKS + 1];
__device__ int    g_idx64;

__device__ __forceinline__ float leaky_exp(float e) {
    e = (e > 0.f) ? e : NEG_SLOPE * e;
    return __expf(e);
}

// ---------------- parallel dtype detection (int32 vs int64) ----------------
__global__ void detect_idx_dtype_par(const int* __restrict__ ei32) {
    __shared__ int nz;
    if (threadIdx.x == 0) nz = 0;
    __syncthreads();
    if (ei32[threadIdx.x * 2 + 1] != 0) atomicAdd(&nz, 1);
    __syncthreads();
    if (threadIdx.x == 0) g_idx64 = (nz == 0);
}

// ---------------- CSR build (latency-optimized: 4 edges/thread, MLP=4) ----------------
__global__ void zero_counts(int* __restrict__ cnt) {
    int i = blockIdx.x * blockDim.x + threadIdx.x;
    if (i < N_NODES) cnt[i] = 0;
}

__global__ void count_edges(const void* __restrict__ ei, int E, int* __restrict__ cnt) {
    int i0 = (blockIdx.x * blockDim.x + threadIdx.x) * 4;
    if (i0 >= E) return;
    int d[4];
    int n = min(4, E - i0);
    if (g_idx64) {
        const long long* p = (const long long*)ei + E;
#pragma unroll
        for (int j = 0; j < 4; j++) if (j < n) d[j] = (int)p[i0 + j];
    } else {
        const int* p = (const int*)ei + E;
#pragma unroll
        for (int j = 0; j < 4; j++) if (j < n) d[j] = p[i0 + j];
    }
#pragma unroll
    for (int j = 0; j < 4; j++) if (j < n) atomicAdd(cnt + d[j], 1);
}

// warp-shuffle two-level scan over SCAN_CHUNK=512 elements
__global__ void scan_block(const int* __restrict__ cnt, int* __restrict__ rowptr,
                           int* __restrict__ bsum) {
    __shared__ int wsum[16];
    int b = blockIdx.x, t = threadIdx.x;
    int lane = t & 31, w = t >> 5;
    int i = b * SCAN_CHUNK + t;
    int v = (i < N_NODES) ? cnt[i] : 0;
    int x = v;
#pragma unroll
    for (int o = 1; o < 32; o <<= 1) {
        int y = __shfl_up_sync(0xffffffffu, x, o);
        if (lane >= o) x += y;
    }
    if (lane == 31) wsum[w] = x;
    __syncthreads();
    if (w == 0) {
        int s = (lane < 16) ? wsum[lane] : 0;
#pragma unroll
        for (int o = 1; o < 16; o <<= 1) {
            int y = __shfl_up_sync(0xffffffffu, s, o);
            if (lane >= o) s += y;
        }
        if (lane < 16) wsum[lane] = s;
    }
    __syncthreads();
    int incl = x + (w > 0 ? wsum[w - 1] : 0);
    if (i < N_NODES) rowptr[i] = incl - v;   // exclusive within block
    if (t == SCAN_CHUNK - 1) bsum[b] = incl;
}

// fused: each block redundantly scans the 98 block sums, then applies offsets
__global__ void add_offsets_fused(int* __restrict__ rowptr, const int* __restrict__ bsum,
                                  int* __restrict__ cur, int E) {
    __shared__ int pref[NUM_SCAN_BLOCKS];
    int t = threadIdx.x;
    if (t < NUM_SCAN_BLOCKS) pref[t] = bsum[t];
    __syncthreads();
    if (t == 0) {
        int a = 0;
        for (int i = 0; i < NUM_SCAN_BLOCKS; i++) { int v = pref[i]; pref[i] = a; a += v; }
    }
    __syncthreads();
    int i = blockIdx.x * blockDim.x + t;
    if (i < N_NODES) {
        int r = rowptr[i] + pref[i / SCAN_CHUNK];
        rowptr[i] = r;
        cur[i] = r;
    }
    if (i == 0) rowptr[N_NODES] = E;
}

__global__ void scatter_edges(const void* __restrict__ ei, int E,
                              int* __restrict__ cur, int* __restrict__ col) {
    int i0 = (blockIdx.x * blockDim.x + threadIdx.x) * 4;
    if (i0 >= E) return;
    int s[4], d[4];
    int n = min(4, E - i0);
    if (g_idx64) {
        const long long* ps = (const long long*)ei;
        const long long* pd = ps + E;
#pragma unroll
        for (int j = 0; j < 4; j++) if (j < n) { s[j] = (int)ps[i0 + j]; d[j] = (int)pd[i0 + j]; }
    } else {
        const int* ps = (const int*)ei;
        const int* pd = ps + E;
#pragma unroll
        for (int j = 0; j < 4; j++) if (j < n) { s[j] = ps[i0 + j]; d[j] = pd[i0 + j]; }
    }
#pragma unroll
    for (int j = 0; j < 4; j++)
        if (j < n) {
            int pos = atomicAdd(cur + d[j], 1);
            col[pos] = s[j];
        }
}

// ---------------- single-term bf16 GEMM, bf16 smem tiles + register-staged pipeline ----------------
__device__ __forceinline__ uint32_t pack_bf16(float v0, float v1) {
    __nv_bfloat162 b2 = __floats2bfloat162_rn(v0, v1);
    return *reinterpret_cast<uint32_t*>(&b2);
}

__device__ __forceinline__ void mma_bf16(float* c, const uint32_t* a, const uint32_t* b) {
    asm volatile(
        "mma.sync.aligned.m16n8k16.row.col.f32.bf16.bf16.f32 "
        "{%0,%1,%2,%3}, {%4,%5,%6,%7}, {%8,%9}, {%0,%1,%2,%3};"
        : "+f"(c[0]), "+f"(c[1]), "+f"(c[2]), "+f"(c[3])
        : "r"(a[0]), "r"(a[1]), "r"(a[2]), "r"(a[3]), "r"(b[0]), "r"(b[1]));
}

// A [M,K] row-major fp32, B [K,N] row-major fp32, C [M,N] fp16. BN==N (single block col).
template <int BM, int BN, int BK>
__global__ void bf16_gemm_dots(const float* __restrict__ A, const float* __restrict__ B,
                               __half* __restrict__ C,
                               const float* __restrict__ att_s, const float* __restrict__ att_d,
                               float* __restrict__ asrc, float* __restrict__ adst,
                               int M, int N, int K) {
    constexpr int WR = 4, WC = 2;
    constexpr int nThreads = WR * WC * 32;
    constexpr int WM = BM / WR;          // 32
    constexpr int WN = BN / WC;          // 64 or 32
    constexpr int MT = WM / 16;          // 2
    constexpr int NT = WN / 8;           // 8 or 4
    constexpr int KS = BK / 16;          // 2
    constexpr int AS = BK + 2;           // 34 bf16
    constexpr int BS = BK + 6;           // 38 bf16
    constexpr int A4  = BM * BK / (4 * nThreads);
    constexpr int BQN = (BK / 2) * (BN / 4) / nThreads;

    extern __shared__ char smemraw[];
    __nv_bfloat16* As = (__nv_bfloat16*)smemraw;                 // [BM][AS]
    __nv_bfloat16* Bs = (__nv_bfloat16*)smemraw + BM * AS;       // [BN][BS]

    int tid = threadIdx.x;
    int wid = tid >> 5;
    int lane = tid & 31;
    int wr = wid / WC, wc = wid % WC;
    int row0 = blockIdx.y * BM;
    int grp = lane >> 2;
    int qd  = lane & 3;

    const int NIT = K / BK;

    float4 aR[A4];
    float4 bR0[BQN], bR1[BQN];

    auto loadRegs = [&](int k0) {
#pragma unroll
        for (int p = 0; p < A4; p++) {
            int i = tid + p * nThreads;
            int r = i / (BK / 4), c4 = i % (BK / 4);
            int gr = row0 + r;
            aR[p] = (gr < M) ? *(const float4*)(A + (size_t)gr * K + k0 + c4 * 4)
                             : make_float4(0.f, 0.f, 0.f, 0.f);
        }
#pragma unroll
        for (int p = 0; p < BQN; p++) {
            int i = tid + p * nThreads;
            int qn = i % (BN / 4), qk = i / (BN / 4);
            int k = qk * 2, n = qn * 4;
            bR0[p] = *(const float4*)(B + (size_t)(k0 + k) * N + n);
            bR1[p] = *(const float4*)(B + (size_t)(k0 + k + 1) * N + n);
        }
    };

    auto storeTiles = [&]() {
#pragma unroll
        for (int p = 0; p < A4; p++) {
            int i = tid + p * nThreads;
            int r = i / (BK / 4), c4 = i % (BK / 4);
            *(uint32_t*)&As[r * AS + c4 * 4]     = pack_bf16(aR[p].x, aR[p].y);
            *(uint32_t*)&As[r * AS + c4 * 4 + 2] = pack_bf16(aR[p].z, aR[p].w);
        }
#pragma unroll
        for (int p = 0; p < BQN; p++) {
            int i = tid + p * nThreads;
            int qn = i % (BN / 4), qk = i / (BN / 4);
            int k = qk * 2, n = qn * 4;
            const float* r0 = &bR0[p].x;
            const float* r1 = &bR1[p].x;
#pragma unroll
            for (int j = 0; j < 4; j++)
                *(uint32_t*)&Bs[(n + j) * BS + k] = pack_bf16(r0[j], r1[j]);
        }
    };

    float acc[MT][NT][4];
#pragma unroll
    for (int i = 0; i < MT; i++)
#pragma unroll
        for (int j = 0; j < NT; j++)
#pragma unroll
            for (int q = 0; q < 4; q++) acc[i][j][q] = 0.f;

    loadRegs(0);

    for (int it = 0; it < NIT; it++) {
        storeTiles();
        __syncthreads();
        if (it + 1 < NIT) loadRegs((it + 1) * BK);

#pragma unroll
        for (int ks = 0; ks < KS; ks++) {
            int kc = ks * 16 + qd * 2;
            uint32_t afrag[MT][4];
#pragma unroll
            for (int mt = 0; mt < MT; mt++) {
                int rb = wr * WM + mt * 16 + grp;
                afrag[mt][0] = *(const uint32_t*)&As[rb * AS + kc];
                afrag[mt][1] = *(const uint32_t*)&As[(rb + 8) * AS + kc];
                afrag[mt][2] = *(const uint32_t*)&As[rb * AS + kc + 8];
                afrag[mt][3] = *(const uint32_t*)&As[(rb + 8) * AS + kc + 8];
            }
#pragma unroll
            for (int nt = 0; nt < NT; nt++) {
                int n = wc * WN + nt * 8 + grp;
                uint32_t bfrag[2];
                bfrag[0] = *(const uint32_t*)&Bs[n * BS + kc];
                bfrag[1] = *(const uint32_t*)&Bs[n * BS + kc + 8];
#pragma unroll
                for (int mt = 0; mt < MT; mt++)
                    mma_bf16(acc[mt][nt], afrag[mt], bfrag);
            }
        }
        __syncthreads();
    }

    // ---- epilogue: fp16 C store + dots via smem block reduction ----
    float* ssm = (float*)smemraw;        // [BM]
    float* sdm = (float*)smemraw + BM;   // [BM]
    if (tid < BM) { ssm[tid] = 0.f; sdm[tid] = 0.f; }
    __syncthreads();

    float ss[MT][2], sd[MT][2];
#pragma unroll
    for (int mt = 0; mt < MT; mt++) { ss[mt][0] = ss[mt][1] = sd[mt][0] = sd[mt][1] = 0.f; }

#pragma unroll
    for (int mt = 0; mt < MT; mt++) {
#pragma unroll
        for (int nt = 0; nt < NT; nt++) {
            int row = row0 + wr * WM + mt * 16 + grp;
            int col = wc * WN + nt * 8 + qd * 2;
            if (row < M)
                *(__half2*)(C + (size_t)row * N + col) =
                    __floats2half2_rn(acc[mt][nt][0], acc[mt][nt][1]);
            if (row + 8 < M)
                *(__half2*)(C + (size_t)(row + 8) * N + col) =
                    __floats2half2_rn(acc[mt][nt][2], acc[mt][nt][3]);

            float a0 = att_s[col], a1 = att_s[col + 1];
            float d0 = att_d[col], d1 = att_d[col + 1];
            ss[mt][0] += acc[mt][nt][0] * a0 + acc[mt][nt][1] * a1;
            ss[mt][1] += acc[mt][nt][2] * a0 + acc[mt][nt][3] * a1;
            sd[mt][0] += acc[mt][nt][0] * d0 + acc[mt][nt][1] * d1;
            sd[mt][1] += acc[mt][nt][2] * d0 + acc[mt][nt][3] * d1;
        }
    }
#pragma unroll
    for (int mt = 0; mt < MT; mt++) {
#pragma unroll
        for (int h = 0; h < 2; h++) {
            float vs = ss[mt][h], vd = sd[mt][h];
            vs += __shfl_xor_sync(0xffffffffu, vs, 1);
            vs += __shfl_xor_sync(0xffffffffu, vs, 2);
            vd += __shfl_xor_sync(0xffffffffu, vd, 1);
            vd += __shfl_xor_sync(0xffffffffu, vd, 2);
            if (qd == 0) {
                int rl = wr * WM + mt * 16 + grp + h * 8;
                atomicAdd(&ssm[rl], vs);
                atomicAdd(&sdm[rl], vd);
            }
        }
    }
    __syncthreads();
    if (tid < BM) {
        int row = row0 + tid;
        if (row < M) { asrc[row] = ssm[tid]; adst[row] = sdm[tid]; }
    }
}

// ---------------- fused gather-aggregate layer 1 (C=128, fp16 h): softmax + bias + ReLU ----------------
__global__ void agg1(const int* __restrict__ rowptr, const int* __restrict__ col,
                     const __half* __restrict__ h, const float* __restrict__ asrc,
                     const float* __restrict__ adst, const float* __restrict__ bias,
                     float* __restrict__ out) {
    int warp = (blockIdx.x * blockDim.x + threadIdx.x) >> 5;
    int lane = threadIdx.x & 31;
    if (warp >= N_NODES) return;
    int d = warp;
    float ad = adst[d];

    float ee = leaky_exp(asrc[d] + ad);
    uint2 u = ((const uint2*)(h + (size_t)d * 128))[lane];
    float2 p0 = __half22float2(*(__half2*)&u.x);
    float2 p1 = __half22float2(*(__half2*)&u.y);
    float ax = p0.x * ee, ay = p0.y * ee, az = p1.x * ee, aw = p1.y * ee;
    float denom = ee;

    int beg = rowptr[d], end = rowptr[d + 1];
    for (int j0 = beg; j0 < end; j0 += 32) {
        int idx = j0 + lane;
        int sj = 0;
        float aj = 0.f;
        if (idx < end) { sj = col[idx]; aj = asrc[sj]; }
        int cnt = min(32, end - j0);
#pragma unroll 4
        for (int j = 0; j < cnt; j++) {
            int s = __shfl_sync(0xffffffffu, sj, j);
            float a = __shfl_sync(0xffffffffu, aj, j);
            float w = leaky_exp(a + ad);
            uint2 ux = ((const uint2*)(h + (size_t)s * 128))[lane];
            float2 x0 = __half22float2(*(__half2*)&ux.x);
            float2 x1 = __half22float2(*(__half2*)&ux.y);
            ax += w * x0.x; ay += w * x0.y; az += w * x1.x; aw += w * x1.y;
            denom += w;
        }
    }
    float inv = 1.f / denom;
    float4 b4 = ((const float4*)bias)[lane];
    float4 o;
    o.x = fmaxf(ax * inv + b4.x, 0.f);
    o.y = fmaxf(ay * inv + b4.y, 0.f);
    o.z = fmaxf(az * inv + b4.z, 0.f);
    o.w = fmaxf(aw * inv + b4.w, 0.f);
    ((float4*)(out + (size_t)d * 128))[lane] = o;
}

// ---------------- fused gather-aggregate layer 2 (C=64, fp16 h): softmax + bias + log_softmax ----------------
__global__ void agg2(const int* __restrict__ rowptr, const int* __restrict__ col,
                     const __half* __restrict__ h, const float* __restrict__ asrc,
                     const float* __restrict__ adst, const float* __restrict__ bias,
                     float* __restrict__ out) {
    int warp = (blockIdx.x * blockDim.x + threadIdx.x) >> 5;
    int lane = threadIdx.x & 31;
    if (warp >= N_NODES) return;
    int d = warp;
    float ad = adst[d];

    float ee = leaky_exp(asrc[d] + ad);
    float2 hv = __half22float2(((const __half2*)(h + (size_t)d * 64))[lane]);
    float ax = hv.x * ee, ay = hv.y * ee;
    float denom = ee;

    int beg = rowptr[d], end = rowptr[d + 1];
    for (int j0 = beg; j0 < end; j0 += 32) {
        int idx = j0 + lane;
        int sj = 0;
        float aj = 0.f;
        if (idx < end) { sj = col[idx]; aj = asrc[sj]; }
        int cnt = min(32, end - j0);
#pragma unroll 4
        for (int j = 0; j < cnt; j++) {
            int s = __shfl_sync(0xffffffffu, sj, j);
            float a = __shfl_sync(0xffffffffu, aj, j);
            float w = leaky_exp(a + ad);
            float2 x = __half22float2(((const __half2*)(h + (size_t)s * 64))[lane]);
            ax += w * x.x; ay += w * x.y;
            denom += w;
        }
    }
    float inv = 1.f / denom;
    float2 b2 = ((const float2*)bias)[lane];
    float v0 = ax * inv + b2.x;
    float v1 = ay * inv + b2.y;
    float m = fmaxf(v0, v1);
#pragma unroll
    for (int o = 16; o > 0; o >>= 1) m = fmaxf(m, __shfl_xor_sync(0xffffffffu, m, o));
    float sm = __expf(v0 - m) + __expf(v1 - m);
#pragma unroll
    for (int o = 16; o > 0; o >>= 1) sm += __shfl_xor_sync(0xffffffffu, sm, o);
    float lse = m + logf(sm);
    float2 o2;
    o2.x = v0 - lse;
    o2.y = v1 - lse;
    ((float2*)(out + (size_t)d * 64))[lane] = o2;
}

// ---------------- host orchestration ----------------
extern "C" void kernel_launch(void* const* d_in, const int* in_sizes, int n_in,
                              void* d_out, int out_size) {
    const float* x   = (const float*)d_in[0];
    const void*  ei  = d_in[1];
    const float* W1  = (const float*)d_in[2];
    const float* as1 = (const float*)d_in[3];
    const float* ad1 = (const float*)d_in[4];
    const float* b1  = (const float*)d_in[5];
    const float* W2  = (const float*)d_in[6];
    const float* as2 = (const float*)d_in[7];
    const float* ad2 = (const float*)d_in[8];
    const float* b2  = (const float*)d_in[9];
    float* out = (float*)d_out;

    int E = in_sizes[1] / 2;

    __half *h1, *h2;
    float *hid, *asrc, *adst, *asrc2, *adst2;
    int *cnt, *rowptr, *cur, *col, *bsum;
    cudaGetSymbolAddress((void**)&h1,  g_h1);
    cudaGetSymbolAddress((void**)&hid, g_hid);
    cudaGetSymbolAddress((void**)&h2,  g_h2);
    cudaGetSymbolAddress((void**)&asrc, g_asrc);
    cudaGetSymbolAddress((void**)&adst, g_adst);
    cudaGetSymbolAddress((void**)&asrc2, g_asrc2);
    cudaGetSymbolAddress((void**)&adst2, g_adst2);
    cudaGetSymbolAddress((void**)&cnt, g_cnt);
    cudaGetSymbolAddress((void**)&rowptr, g_rowptr);
    cudaGetSymbolAddress((void**)&cur, g_cur);
    cudaGetSymbolAddress((void**)&col, g_col);
    cudaGetSymbolAddress((void**)&bsum, g_bsum);

    // bf16 smem tiles: A [BM][BK+2], B [BN][BK+6]
    const int SMEM1 = (128 * 34 + 128 * 38) * 2;  // 18432 B
    const int SMEM2 = (128 * 34 + 64 * 38) * 2;   // 13568 B

    static cudaStream_t s_side = nullptr;
    static cudaEvent_t ev_fork = nullptr, ev_join = nullptr;
    if (!s_side) {
        cudaStreamCreateWithFlags(&s_side, cudaStreamNonBlocking);
        cudaEventCreateWithFlags(&ev_fork, cudaEventDisableTiming);
        cudaEventCreateWithFlags(&ev_join, cudaEventDisableTiming);
    }

    const int nodeBlocks = (N_NODES + 255) / 256;
    const int nodeWarpBlocks = (N_NODES * 32 + 255) / 256;
    const int edgeBlocks4 = (E + 1023) / 1024;   // 4 edges/thread

    // ---- fork immediately: detect + CSR build on side stream, concurrent with gemm1 ----
    cudaEventRecord(ev_fork, 0);
    cudaStreamWaitEvent(s_side, ev_fork, 0);

    zero_counts<<<nodeBlocks, 256, 0, s_side>>>(cnt);
    detect_idx_dtype_par<<<1, 128, 0, s_side>>>((const int*)ei);
    count_edges<<<edgeBlocks4, 256, 0, s_side>>>(ei, E, cnt);
    scan_block<<<NUM_SCAN_BLOCKS, SCAN_CHUNK, 0, s_side>>>(cnt, rowptr, bsum);
    add_offsets_fused<<<nodeBlocks, 256, 0, s_side>>>(rowptr, bsum, cur, E);
    scatter_edges<<<edgeBlocks4, 256, 0, s_side>>>(ei, E, cur, col);
    cudaEventRecord(ev_join, s_side);

    // ---- main stream: layer-1 GEMM with fused dots ----
    {
        dim3 grid(1, (N_NODES + 127) / 128);
        bf16_gemm_dots<128, 128, 32><<<grid, 256, SMEM1>>>(x, W1, h1, as1, ad1, asrc, adst,
                                                           N_NODES, 128, 256);
    }

    // ---- join, then aggregate layer 1 ----
    cudaStreamWaitEvent(0, ev_join, 0);
    agg1<<<nodeWarpBlocks, 256>>>(rowptr, col, h1, asrc, adst, b1, hid);

    // ---- layer 2 ----
    {
        dim3 grid(1, (N_NODES + 127) / 128);
        bf16_gemm_dots<128, 64, 32><<<grid, 256, SMEM2>>>(hid, W2, h2, as2, ad2, asrc2, adst2,
                                                          N_NODES, 64, 128);
    }
    agg2<<<nodeWarpBlocks, 256>>>(rowptr, col, h2, asrc2, adst2, b2, out);
}